// round 4
// baseline (speedup 1.0000x reference)
#include <cuda_runtime.h>

#define NPTS 8192
#define D 64
#define SCALE 0.125f   // 1/sqrt(64)

// ---------------- scratch (device globals; no allocations allowed) ----------
__device__ float g_q[2][NPTS * D];
__device__ float g_k[2][NPTS * D];
__device__ float g_att[2][NPTS * D];
__device__ float g_nrm[2][NPTS];

// XOR swizzle at float4 granularity for [64][64] fp32 tiles stored k-major.
// chunk index for (k, row-chunk c4): conflict-free vectorized loads.
__device__ __forceinline__ int sw64(int k, int c4) { return k * 16 + (c4 ^ (k & 15)); }
// same for [64][128] tiles (32 chunks per k-row)
__device__ __forceinline__ int sw128(int k, int c4) { return k * 32 + (c4 ^ (k & 31)); }

// ---------------- 1) projections: Q = X@Wq, K = X@Wk for both inputs -------
__global__ void proj_kernel(const float* __restrict__ x, const float* __restrict__ y,
                            const float* __restrict__ Wq, const float* __restrict__ Wk)
{
    __shared__ float wq[D * D], wk[D * D];
    __shared__ float xs[4][D];
    int tx = threadIdx.x;           // 0..63  (output column)
    int ty = threadIdx.y;           // 0..3   (row within block)
    int tid = ty * D + tx;
    for (int i = tid; i < D * D; i += 256) { wq[i] = Wq[i]; wk[i] = Wk[i]; }

    int w = blockIdx.y;
    const float* in = w ? y : x;
    int row = blockIdx.x * 4 + ty;
    xs[ty][tx] = in[row * D + tx];
    __syncthreads();

    float aq = 0.f, ak = 0.f;
#pragma unroll
    for (int k = 0; k < D; k++) {
        float v = xs[ty][k];
        aq = fmaf(v, wq[k * D + tx], aq);
        ak = fmaf(v, wk[k * D + tx], ak);
    }
    g_q[w][row * D + tx] = aq;
    g_k[w][row * D + tx] = ak;
}

// ---------------- 2) flash attention (BM = BN = 64, 256 threads) -----------
// thread (tx = tid&15, ty = tid>>4): owns S rows ty*4..+3, cols tx*4..+3,
// and O rows ty*4..+3, dims tx*4..+3. Shuffle reductions over the tx group.
__global__ __launch_bounds__(256, 2)
void attn_kernel(const float* __restrict__ x, const float* __restrict__ y)
{
    extern __shared__ float4 sm[];
    float4* Qs = sm;          // [64][16] chunks, swizzled, k-major
    float4* Ks = sm + 1024;   // same
    float4* Vs = sm + 2048;   // [j][16] chunks, swizzled (row-major over d)
    float4* Ps = sm + 3072;   // [j][16] chunks over rows, swizzled

    int tid = threadIdx.x;
    int tx = tid & 15, ty = tid >> 4;
    int w = blockIdx.y;
    const float* Vg = w ? y : x;
    const float* Qg = g_q[w];
    const float* Kg = g_k[w];
    int rowblk = blockIdx.x * 64;

    // load Q tile: transpose to k-major with swizzle
    for (int e = tid; e < 4096; e += 256) {
        int r = e >> 6, c = e & 63;
        ((float*)Qs)[sw64(c, r >> 2) * 4 + (r & 3)] = Qg[(rowblk + r) * D + c];
    }

    float o[4][4], m[4], l[4];
#pragma unroll
    for (int rr = 0; rr < 4; rr++) {
        m[rr] = -1e30f; l[rr] = 0.f;
#pragma unroll
        for (int cc = 0; cc < 4; cc++) o[rr][cc] = 0.f;
    }

    for (int t = 0; t < NPTS / 64; t++) {
        int kb = t * 64;
        __syncthreads();   // protects Ks/Vs/Ps reuse from previous iteration
        for (int e = tid; e < 4096; e += 256) {
            int r = e >> 6, c = e & 63;
            ((float*)Ks)[sw64(c, r >> 2) * 4 + (r & 3)] = Kg[kb * D + e];
        }
        const float4* Vg4 = (const float4*)(Vg + kb * D);
        for (int e4 = tid; e4 < 1024; e4 += 256) {
            int j = e4 >> 4, d4 = e4 & 15;
            Vs[sw64(j, d4)] = Vg4[e4];
        }
        __syncthreads();

        // S = Q @ K^T  (raw scores; scale applied inside exp)
        float s[4][4];
#pragma unroll
        for (int rr = 0; rr < 4; rr++)
#pragma unroll
            for (int cc = 0; cc < 4; cc++) s[rr][cc] = 0.f;

#pragma unroll 16
        for (int k = 0; k < 64; k++) {
            float4 a = Qs[sw64(k, ty)];
            float4 b = Ks[sw64(k, tx)];
            float av[4] = {a.x, a.y, a.z, a.w};
            float bv[4] = {b.x, b.y, b.z, b.w};
#pragma unroll
            for (int rr = 0; rr < 4; rr++)
#pragma unroll
                for (int cc = 0; cc < 4; cc++)
                    s[rr][cc] = fmaf(av[rr], bv[cc], s[rr][cc]);
        }

        // online softmax (per row; stats replicated across the 16 tx lanes)
#pragma unroll
        for (int rr = 0; rr < 4; rr++) {
            float mt = fmaxf(fmaxf(s[rr][0], s[rr][1]), fmaxf(s[rr][2], s[rr][3]));
#pragma unroll
            for (int msk = 8; msk; msk >>= 1)
                mt = fmaxf(mt, __shfl_xor_sync(0xffffffffu, mt, msk));
            float mn = fmaxf(m[rr], mt);
            float corr = __expf((m[rr] - mn) * SCALE);
            float rs = 0.f;
#pragma unroll
            for (int cc = 0; cc < 4; cc++) {
                s[rr][cc] = __expf((s[rr][cc] - mn) * SCALE);
                rs += s[rr][cc];
            }
#pragma unroll
            for (int msk = 8; msk; msk >>= 1)
                rs += __shfl_xor_sync(0xffffffffu, rs, msk);
            l[rr] = l[rr] * corr + rs;
            m[rr] = mn;
#pragma unroll
            for (int cc = 0; cc < 4; cc++) o[rr][cc] *= corr;
        }

        // stage P into smem (vectorized over the 4 owned rows)
#pragma unroll
        for (int cc = 0; cc < 4; cc++)
            Ps[sw64(tx * 4 + cc, ty)] =
                make_float4(s[0][cc], s[1][cc], s[2][cc], s[3][cc]);
        __syncthreads();

        // O += P @ V
#pragma unroll 16
        for (int j = 0; j < 64; j++) {
            float4 a = Ps[sw64(j, ty)];
            float4 b = Vs[sw64(j, tx)];
            float av[4] = {a.x, a.y, a.z, a.w};
            float bv[4] = {b.x, b.y, b.z, b.w};
#pragma unroll
            for (int rr = 0; rr < 4; rr++)
#pragma unroll
                for (int cc = 0; cc < 4; cc++)
                    o[rr][cc] = fmaf(av[rr], bv[cc], o[rr][cc]);
        }
    }

    // epilogue: normalize, store att, store row norms
    float* Ag = g_att[w];
#pragma unroll
    for (int rr = 0; rr < 4; rr++) {
        int row = rowblk + ty * 4 + rr;
        float inv = 1.f / l[rr];
        float4 v = make_float4(o[rr][0] * inv, o[rr][1] * inv,
                               o[rr][2] * inv, o[rr][3] * inv);
        *(float4*)(Ag + row * D + tx * 4) = v;
        float n = v.x * v.x + v.y * v.y + v.z * v.z + v.w * v.w;
#pragma unroll
        for (int msk = 8; msk; msk >>= 1)
            n += __shfl_xor_sync(0xffffffffu, n, msk);
        if (tx == 0) g_nrm[w][row] = n;
    }
}

// ---------------- 3) pairwise RBF: out[i][j] = exp(2*dot - nx - ny) --------
// 128x128 output tile per CTA, 256 threads, 8x8 microtile (split 4+4).
__global__ __launch_bounds__(256, 2)
void pair_kernel(float* __restrict__ out)
{
    extern __shared__ float4 sm[];
    float4* XA = sm;          // [k=64][32] chunks, swizzled
    float4* YA = sm + 2048;

    int tid = threadIdx.x;
    int tx = tid & 15, ty = tid >> 4;
    int i0 = blockIdx.x * 128, j0 = blockIdx.y * 128;
    const float* xa = g_att[0];
    const float* ya = g_att[1];

    for (int e = tid; e < 8192; e += 256) {
        int r = e >> 6, c = e & 63;
        ((float*)XA)[sw128(c, r >> 2) * 4 + (r & 3)] = xa[(i0 + r) * D + c];
        ((float*)YA)[sw128(c, r >> 2) * 4 + (r & 3)] = ya[(j0 + r) * D + c];
    }

    float acc[8][8];
#pragma unroll
    for (int rr = 0; rr < 8; rr++)
#pragma unroll
        for (int cc = 0; cc < 8; cc++) acc[rr][cc] = 0.f;
    __syncthreads();

#pragma unroll 8
    for (int k = 0; k < 64; k++) {
        float4 a0 = XA[sw128(k, ty)];
        float4 a1 = XA[sw128(k, 16 + ty)];
        float4 b0 = YA[sw128(k, tx)];
        float4 b1 = YA[sw128(k, 16 + tx)];
        float av[8] = {a0.x, a0.y, a0.z, a0.w, a1.x, a1.y, a1.z, a1.w};
        float bv[8] = {b0.x, b0.y, b0.z, b0.w, b1.x, b1.y, b1.z, b1.w};
#pragma unroll
        for (int rr = 0; rr < 8; rr++)
#pragma unroll
            for (int cc = 0; cc < 8; cc++)
                acc[rr][cc] = fmaf(av[rr], bv[cc], acc[rr][cc]);
    }

    int ri[8], cj[8];
    float nx[8], ny[8];
#pragma unroll
    for (int q = 0; q < 8; q++) {
        ri[q] = i0 + ((q < 4) ? (ty * 4 + q) : (64 + ty * 4 + q - 4));
        cj[q] = j0 + ((q < 4) ? (tx * 4 + q) : (64 + tx * 4 + q - 4));
        nx[q] = g_nrm[0][ri[q]];
        ny[q] = g_nrm[1][cj[q]];
    }

#pragma unroll
    for (int rr = 0; rr < 8; rr++) {
        float4 v0 = make_float4(__expf(2.f * acc[rr][0] - nx[rr] - ny[0]),
                                __expf(2.f * acc[rr][1] - nx[rr] - ny[1]),
                                __expf(2.f * acc[rr][2] - nx[rr] - ny[2]),
                                __expf(2.f * acc[rr][3] - nx[rr] - ny[3]));
        float4 v1 = make_float4(__expf(2.f * acc[rr][4] - nx[rr] - ny[4]),
                                __expf(2.f * acc[rr][5] - nx[rr] - ny[5]),
                                __expf(2.f * acc[rr][6] - nx[rr] - ny[6]),
                                __expf(2.f * acc[rr][7] - nx[rr] - ny[7]));
        float* rowp = out + (size_t)ri[rr] * NPTS;
        *(float4*)(rowp + j0 + tx * 4) = v0;
        *(float4*)(rowp + j0 + 64 + tx * 4) = v1;
    }
}

// ---------------- launcher -------------------------------------------------
extern "C" void kernel_launch(void* const* d_in, const int* in_sizes, int n_in,
                              void* d_out, int out_size)
{
    const float* Wq = (const float*)d_in[0];   // rotation_params
    const float* Wk = (const float*)d_in[1];   // entangle_params
    const float* x  = (const float*)d_in[2];
    const float* y  = (const float*)d_in[3];
    float* out = (float*)d_out;

    // 64 KB dynamic smem per CTA (idempotent; legal outside stream capture scope)
    cudaFuncSetAttribute(attn_kernel, cudaFuncAttributeMaxDynamicSharedMemorySize, 64 * 1024);
    cudaFuncSetAttribute(pair_kernel, cudaFuncAttributeMaxDynamicSharedMemorySize, 64 * 1024);

    proj_kernel<<<dim3(NPTS / 4, 2), dim3(64, 4)>>>(x, y, Wq, Wk);
    attn_kernel<<<dim3(NPTS / 64, 2), 256, 64 * 1024>>>(x, y);
    pair_kernel<<<dim3(NPTS / 128, NPTS / 128), 256, 64 * 1024>>>(out);
}

// round 5
// speedup vs baseline: 1.0908x; 1.0908x over previous
#include <cuda_runtime.h>

#define NPTS 8192
#define D 64
#define SCALE 0.125f   // 1/sqrt(64)

typedef unsigned long long u64;

// ---------------- packed fp32x2 helpers (Blackwell FFMA2 path) -------------
__device__ __forceinline__ u64 dup2(float v) {
    u64 r; asm("mov.b64 %0, {%1, %1};" : "=l"(r) : "f"(v)); return r;
}
__device__ __forceinline__ void ffma2(u64& d, u64 a, u64 b) {
    asm("fma.rn.f32x2 %0, %1, %2, %0;" : "+l"(d) : "l"(a), "l"(b));
}
__device__ __forceinline__ void mul2(u64& d, u64 c) {
    asm("mul.rn.f32x2 %0, %0, %1;" : "+l"(d) : "l"(c));
}
__device__ __forceinline__ float2 unpk(u64 v) {
    float lo, hi; asm("mov.b64 {%0, %1}, %2;" : "=f"(lo), "=f"(hi) : "l"(v));
    return make_float2(lo, hi);
}

// ---------------- scratch (device globals; no allocations allowed) ----------
__device__ float g_q[2][NPTS * D];
__device__ float g_k[2][NPTS * D];
__device__ float g_att[2][NPTS * D];
__device__ float g_nrm[2][NPTS];

// XOR swizzle at float4 granularity for [64][64] fp32 tiles stored k-major.
__device__ __forceinline__ int sw64(int k, int c4) { return k * 16 + (c4 ^ (k & 15)); }
// same for [64][128] tiles (32 chunks per k-row)
__device__ __forceinline__ int sw128(int k, int c4) { return k * 32 + (c4 ^ (k & 31)); }

// ---------------- 1) projections: Q = X@Wq, K = X@Wk for both inputs -------
// 64 rows per CTA: W loaded once per 64 rows (16x less L2 traffic than before).
__global__ void proj_kernel(const float* __restrict__ x, const float* __restrict__ y,
                            const float* __restrict__ Wq, const float* __restrict__ Wk)
{
    __shared__ float wq[D * D], wk[D * D];
    __shared__ float xs[64][D];
    int tx = threadIdx.x;           // 0..63  (output column)
    int ty = threadIdx.y;           // 0..3
    int tid = ty * D + tx;
    for (int i = tid; i < D * D; i += 256) { wq[i] = Wq[i]; wk[i] = Wk[i]; }

    int w = blockIdx.y;
    const float* in = w ? y : x;
    int row0 = blockIdx.x * 64;
    for (int e = tid; e < 64 * D; e += 256)
        ((float*)xs)[e] = in[row0 * D + e];
    __syncthreads();

    for (int rl = ty; rl < 64; rl += 4) {
        float aq = 0.f, ak = 0.f;
#pragma unroll
        for (int k = 0; k < D; k++) {
            float v = xs[rl][k];
            aq = fmaf(v, wq[k * D + tx], aq);
            ak = fmaf(v, wk[k * D + tx], ak);
        }
        int row = row0 + rl;
        g_q[w][row * D + tx] = aq;
        g_k[w][row * D + tx] = ak;
    }
}

// ---------------- 2) flash attention (BM = BN = 64, 256 threads) -----------
// thread (tx = tid&15, ty = tid>>4): owns S rows ty*4..+3, cols tx*4..+3,
// and O rows ty*4..+3, dims tx*4..+3. GEMMs use packed fp32x2 (FFMA2).
__global__ __launch_bounds__(256, 2)
void attn_kernel(const float* __restrict__ x, const float* __restrict__ y)
{
    extern __shared__ float4 sm[];
    float4* Qs = sm;          // [64][16] chunks, swizzled, k-major
    float4* Ks = sm + 1024;   // same
    float4* Vs = sm + 2048;   // [j][16] chunks, swizzled (row-major over d)
    float4* Ps = sm + 3072;   // [j][16] chunks over rows, swizzled

    int tid = threadIdx.x;
    int tx = tid & 15, ty = tid >> 4;
    int w = blockIdx.y;
    const float* Vg = w ? y : x;
    const float* Qg = g_q[w];
    const float* Kg = g_k[w];
    int rowblk = blockIdx.x * 64;

    // load Q tile: transpose to k-major with swizzle
    for (int e = tid; e < 4096; e += 256) {
        int r = e >> 6, c = e & 63;
        ((float*)Qs)[sw64(c, r >> 2) * 4 + (r & 3)] = Qg[(rowblk + r) * D + c];
    }

    u64 o2[4][2];           // packed O accumulators: [row][dim-pair]
    float m[4], l[4];
#pragma unroll
    for (int rr = 0; rr < 4; rr++) {
        m[rr] = -1e30f; l[rr] = 0.f;
        o2[rr][0] = 0ull; o2[rr][1] = 0ull;
    }

    for (int t = 0; t < NPTS / 64; t++) {
        int kb = t * 64;
        __syncthreads();   // protects Ks/Vs/Ps reuse from previous iteration
        for (int e = tid; e < 4096; e += 256) {
            int r = e >> 6, c = e & 63;
            ((float*)Ks)[sw64(c, r >> 2) * 4 + (r & 3)] = Kg[kb * D + e];
        }
        const float4* Vg4 = (const float4*)(Vg + kb * D);
        for (int e4 = tid; e4 < 1024; e4 += 256) {
            int j = e4 >> 4, d4 = e4 & 15;
            Vs[sw64(j, d4)] = Vg4[e4];
        }
        __syncthreads();

        // S = Q @ K^T  (raw scores; scale applied inside exp) — packed FFMA2
        u64 s2[4][2];
#pragma unroll
        for (int rr = 0; rr < 4; rr++) { s2[rr][0] = 0ull; s2[rr][1] = 0ull; }

#pragma unroll 16
        for (int k = 0; k < 64; k++) {
            float4 a = Qs[sw64(k, ty)];
            ulonglong2 b = *(const ulonglong2*)(Ks + sw64(k, tx));
            u64 ar[4] = {dup2(a.x), dup2(a.y), dup2(a.z), dup2(a.w)};
#pragma unroll
            for (int rr = 0; rr < 4; rr++) {
                ffma2(s2[rr][0], ar[rr], b.x);
                ffma2(s2[rr][1], ar[rr], b.y);
            }
        }

        // unpack to scalars for softmax
        float s[4][4];
#pragma unroll
        for (int rr = 0; rr < 4; rr++) {
            float2 v0 = unpk(s2[rr][0]), v1 = unpk(s2[rr][1]);
            s[rr][0] = v0.x; s[rr][1] = v0.y; s[rr][2] = v1.x; s[rr][3] = v1.y;
        }

        // online softmax (per row; stats replicated across the 16 tx lanes)
#pragma unroll
        for (int rr = 0; rr < 4; rr++) {
            float mt = fmaxf(fmaxf(s[rr][0], s[rr][1]), fmaxf(s[rr][2], s[rr][3]));
#pragma unroll
            for (int msk = 8; msk; msk >>= 1)
                mt = fmaxf(mt, __shfl_xor_sync(0xffffffffu, mt, msk));
            float mn = fmaxf(m[rr], mt);
            float corr = __expf((m[rr] - mn) * SCALE);
            float rs = 0.f;
#pragma unroll
            for (int cc = 0; cc < 4; cc++) {
                s[rr][cc] = __expf((s[rr][cc] - mn) * SCALE);
                rs += s[rr][cc];
            }
#pragma unroll
            for (int msk = 8; msk; msk >>= 1)
                rs += __shfl_xor_sync(0xffffffffu, rs, msk);
            l[rr] = l[rr] * corr + rs;
            m[rr] = mn;
            u64 c2 = dup2(corr);
            mul2(o2[rr][0], c2);
            mul2(o2[rr][1], c2);
        }

        // stage P into smem (vectorized over the 4 owned rows)
#pragma unroll
        for (int cc = 0; cc < 4; cc++)
            Ps[sw64(tx * 4 + cc, ty)] =
                make_float4(s[0][cc], s[1][cc], s[2][cc], s[3][cc]);
        __syncthreads();

        // O += P @ V — packed FFMA2
#pragma unroll 16
        for (int j = 0; j < 64; j++) {
            float4 a = Ps[sw64(j, ty)];
            ulonglong2 b = *(const ulonglong2*)(Vs + sw64(j, tx));
            u64 ar[4] = {dup2(a.x), dup2(a.y), dup2(a.z), dup2(a.w)};
#pragma unroll
            for (int rr = 0; rr < 4; rr++) {
                ffma2(o2[rr][0], ar[rr], b.x);
                ffma2(o2[rr][1], ar[rr], b.y);
            }
        }
    }

    // epilogue: normalize, store att, store row norms
    float* Ag = g_att[w];
#pragma unroll
    for (int rr = 0; rr < 4; rr++) {
        int row = rowblk + ty * 4 + rr;
        float inv = 1.f / l[rr];
        float2 p0 = unpk(o2[rr][0]), p1 = unpk(o2[rr][1]);
        float4 v = make_float4(p0.x * inv, p0.y * inv, p1.x * inv, p1.y * inv);
        *(float4*)(Ag + row * D + tx * 4) = v;
        float n = v.x * v.x + v.y * v.y + v.z * v.z + v.w * v.w;
#pragma unroll
        for (int msk = 8; msk; msk >>= 1)
            n += __shfl_xor_sync(0xffffffffu, n, msk);
        if (tx == 0) g_nrm[w][row] = n;
    }
}

// ---------------- 3) pairwise RBF: out[i][j] = exp(2*dot - nx - ny) --------
// 128x128 output tile per CTA, 256 threads, 8x8 microtile, packed FFMA2.
__global__ __launch_bounds__(256, 2)
void pair_kernel(float* __restrict__ out)
{
    extern __shared__ float4 sm[];
    float4* XA = sm;          // [k=64][32] chunks, swizzled
    float4* YA = sm + 2048;

    int tid = threadIdx.x;
    int tx = tid & 15, ty = tid >> 4;
    int i0 = blockIdx.x * 128, j0 = blockIdx.y * 128;
    const float* xa = g_att[0];
    const float* ya = g_att[1];

    for (int e = tid; e < 8192; e += 256) {
        int r = e >> 6, c = e & 63;
        ((float*)XA)[sw128(c, r >> 2) * 4 + (r & 3)] = xa[(i0 + r) * D + c];
        ((float*)YA)[sw128(c, r >> 2) * 4 + (r & 3)] = ya[(j0 + r) * D + c];
    }

    u64 acc2[8][4];           // [row][col-pair]
#pragma unroll
    for (int rr = 0; rr < 8; rr++)
#pragma unroll
        for (int p = 0; p < 4; p++) acc2[rr][p] = 0ull;
    __syncthreads();

#pragma unroll 8
    for (int k = 0; k < 64; k++) {
        float4 a0 = XA[sw128(k, ty)];
        float4 a1 = XA[sw128(k, 16 + ty)];
        ulonglong2 b0 = *(const ulonglong2*)(YA + sw128(k, tx));
        ulonglong2 b1 = *(const ulonglong2*)(YA + sw128(k, 16 + tx));
        u64 ar[8] = {dup2(a0.x), dup2(a0.y), dup2(a0.z), dup2(a0.w),
                     dup2(a1.x), dup2(a1.y), dup2(a1.z), dup2(a1.w)};
#pragma unroll
        for (int rr = 0; rr < 8; rr++) {
            ffma2(acc2[rr][0], ar[rr], b0.x);
            ffma2(acc2[rr][1], ar[rr], b0.y);
            ffma2(acc2[rr][2], ar[rr], b1.x);
            ffma2(acc2[rr][3], ar[rr], b1.y);
        }
    }

    float acc[8][8];
#pragma unroll
    for (int rr = 0; rr < 8; rr++)
#pragma unroll
        for (int p = 0; p < 4; p++) {
            float2 v = unpk(acc2[rr][p]);
            acc[rr][2 * p] = v.x; acc[rr][2 * p + 1] = v.y;
        }

    int ri[8], cj[8];
    float nx[8], ny[8];
#pragma unroll
    for (int q = 0; q < 8; q++) {
        ri[q] = i0 + ((q < 4) ? (ty * 4 + q) : (64 + ty * 4 + q - 4));
        cj[q] = j0 + ((q < 4) ? (tx * 4 + q) : (64 + tx * 4 + q - 4));
        nx[q] = g_nrm[0][ri[q]];
        ny[q] = g_nrm[1][cj[q]];
    }

#pragma unroll
    for (int rr = 0; rr < 8; rr++) {
        float4 v0 = make_float4(__expf(2.f * acc[rr][0] - nx[rr] - ny[0]),
                                __expf(2.f * acc[rr][1] - nx[rr] - ny[1]),
                                __expf(2.f * acc[rr][2] - nx[rr] - ny[2]),
                                __expf(2.f * acc[rr][3] - nx[rr] - ny[3]));
        float4 v1 = make_float4(__expf(2.f * acc[rr][4] - nx[rr] - ny[4]),
                                __expf(2.f * acc[rr][5] - nx[rr] - ny[5]),
                                __expf(2.f * acc[rr][6] - nx[rr] - ny[6]),
                                __expf(2.f * acc[rr][7] - nx[rr] - ny[7]));
        float* rowp = out + (size_t)ri[rr] * NPTS;
        *(float4*)(rowp + j0 + tx * 4) = v0;
        *(float4*)(rowp + j0 + 64 + tx * 4) = v1;
    }
}

// ---------------- launcher -------------------------------------------------
extern "C" void kernel_launch(void* const* d_in, const int* in_sizes, int n_in,
                              void* d_out, int out_size)
{
    const float* Wq = (const float*)d_in[0];   // rotation_params
    const float* Wk = (const float*)d_in[1];   // entangle_params
    const float* x  = (const float*)d_in[2];
    const float* y  = (const float*)d_in[3];
    float* out = (float*)d_out;

    cudaFuncSetAttribute(attn_kernel, cudaFuncAttributeMaxDynamicSharedMemorySize, 64 * 1024);
    cudaFuncSetAttribute(pair_kernel, cudaFuncAttributeMaxDynamicSharedMemorySize, 64 * 1024);

    proj_kernel<<<dim3(NPTS / 64, 2), dim3(64, 4)>>>(x, y, Wq, Wk);
    attn_kernel<<<dim3(NPTS / 64, 2), 256, 64 * 1024>>>(x, y);
    pair_kernel<<<dim3(NPTS / 128, NPTS / 128), 256, 64 * 1024>>>(out);
}

// round 6
// speedup vs baseline: 1.0909x; 1.0001x over previous
#include <cuda_runtime.h>

#define NPTS 8192
#define D 64
#define SCALE 0.125f   // 1/sqrt(64)

typedef unsigned long long u64;

// ---------------- packed fp32x2 helpers (Blackwell FFMA2 path) -------------
__device__ __forceinline__ u64 dup2(float v) {
    u64 r; asm("mov.b64 %0, {%1, %1};" : "=l"(r) : "f"(v)); return r;
}
__device__ __forceinline__ void ffma2(u64& d, u64 a, u64 b) {
    asm("fma.rn.f32x2 %0, %1, %2, %0;" : "+l"(d) : "l"(a), "l"(b));
}
__device__ __forceinline__ void mul2(u64& d, u64 c) {
    asm("mul.rn.f32x2 %0, %0, %1;" : "+l"(d) : "l"(c));
}
__device__ __forceinline__ float2 unpk(u64 v) {
    float lo, hi; asm("mov.b64 {%0, %1}, %2;" : "=f"(lo), "=f"(hi) : "l"(v));
    return make_float2(lo, hi);
}

// ---------------- scratch (device globals; no allocations allowed) ----------
__device__ float g_q[2][NPTS * D];
__device__ float g_k[2][NPTS * D];
__device__ float g_att[2][NPTS * D];
__device__ float g_nrm[2][NPTS];

// XOR swizzle at float4 granularity for [64][64] fp32 tiles stored k-major.
__device__ __forceinline__ int sw64(int k, int c4) { return k * 16 + (c4 ^ (k & 15)); }
// same for [64][128] tiles (32 chunks per k-row)
__device__ __forceinline__ int sw128(int k, int c4) { return k * 32 + (c4 ^ (k & 31)); }

// ---------------- 1) projections: Q = X@Wq, K = X@Wk for both inputs -------
// 64 rows per CTA: W loaded once per 64 rows (16x less L2 traffic than before).
__global__ void proj_kernel(const float* __restrict__ x, const float* __restrict__ y,
                            const float* __restrict__ Wq, const float* __restrict__ Wk)
{
    __shared__ float wq[D * D], wk[D * D];
    __shared__ float xs[64][D];
    int tx = threadIdx.x;           // 0..63  (output column)
    int ty = threadIdx.y;           // 0..3
    int tid = ty * D + tx;
    for (int i = tid; i < D * D; i += 256) { wq[i] = Wq[i]; wk[i] = Wk[i]; }

    int w = blockIdx.y;
    const float* in = w ? y : x;
    int row0 = blockIdx.x * 64;
    for (int e = tid; e < 64 * D; e += 256)
        ((float*)xs)[e] = in[row0 * D + e];
    __syncthreads();

    for (int rl = ty; rl < 64; rl += 4) {
        float aq = 0.f, ak = 0.f;
#pragma unroll
        for (int k = 0; k < D; k++) {
            float v = xs[rl][k];
            aq = fmaf(v, wq[k * D + tx], aq);
            ak = fmaf(v, wk[k * D + tx], ak);
        }
        int row = row0 + rl;
        g_q[w][row * D + tx] = aq;
        g_k[w][row * D + tx] = ak;
    }
}

// ---------------- 2) flash attention (BM = BN = 64, 256 threads) -----------
// thread (tx = tid&15, ty = tid>>4): owns S rows ty*4..+3, cols tx*4..+3,
// and O rows ty*4..+3, dims tx*4..+3. GEMMs use packed fp32x2 (FFMA2).
__global__ __launch_bounds__(256, 2)
void attn_kernel(const float* __restrict__ x, const float* __restrict__ y)
{
    extern __shared__ float4 sm[];
    float4* Qs = sm;          // [64][16] chunks, swizzled, k-major
    float4* Ks = sm + 1024;   // same
    float4* Vs = sm + 2048;   // [j][16] chunks, swizzled (row-major over d)
    float4* Ps = sm + 3072;   // [j][16] chunks over rows, swizzled

    int tid = threadIdx.x;
    int tx = tid & 15, ty = tid >> 4;
    int w = blockIdx.y;
    const float* Vg = w ? y : x;
    const float* Qg = g_q[w];
    const float* Kg = g_k[w];
    int rowblk = blockIdx.x * 64;

    // load Q tile: transpose to k-major with swizzle
    for (int e = tid; e < 4096; e += 256) {
        int r = e >> 6, c = e & 63;
        ((float*)Qs)[sw64(c, r >> 2) * 4 + (r & 3)] = Qg[(rowblk + r) * D + c];
    }

    u64 o2[4][2];           // packed O accumulators: [row][dim-pair]
    float m[4], l[4];
#pragma unroll
    for (int rr = 0; rr < 4; rr++) {
        m[rr] = -1e30f; l[rr] = 0.f;
        o2[rr][0] = 0ull; o2[rr][1] = 0ull;
    }

    for (int t = 0; t < NPTS / 64; t++) {
        int kb = t * 64;
        __syncthreads();   // protects Ks/Vs/Ps reuse from previous iteration
        for (int e = tid; e < 4096; e += 256) {
            int r = e >> 6, c = e & 63;
            ((float*)Ks)[sw64(c, r >> 2) * 4 + (r & 3)] = Kg[kb * D + e];
        }
        const float4* Vg4 = (const float4*)(Vg + kb * D);
        for (int e4 = tid; e4 < 1024; e4 += 256) {
            int j = e4 >> 4, d4 = e4 & 15;
            Vs[sw64(j, d4)] = Vg4[e4];
        }
        __syncthreads();

        // S = Q @ K^T  (raw scores; scale applied inside exp) — packed FFMA2
        u64 s2[4][2];
#pragma unroll
        for (int rr = 0; rr < 4; rr++) { s2[rr][0] = 0ull; s2[rr][1] = 0ull; }

#pragma unroll 16
        for (int k = 0; k < 64; k++) {
            float4 a = Qs[sw64(k, ty)];
            ulonglong2 b = *(const ulonglong2*)(Ks + sw64(k, tx));
            u64 ar[4] = {dup2(a.x), dup2(a.y), dup2(a.z), dup2(a.w)};
#pragma unroll
            for (int rr = 0; rr < 4; rr++) {
                ffma2(s2[rr][0], ar[rr], b.x);
                ffma2(s2[rr][1], ar[rr], b.y);
            }
        }

        // unpack to scalars for softmax
        float s[4][4];
#pragma unroll
        for (int rr = 0; rr < 4; rr++) {
            float2 v0 = unpk(s2[rr][0]), v1 = unpk(s2[rr][1]);
            s[rr][0] = v0.x; s[rr][1] = v0.y; s[rr][2] = v1.x; s[rr][3] = v1.y;
        }

        // online softmax (per row; stats replicated across the 16 tx lanes)
#pragma unroll
        for (int rr = 0; rr < 4; rr++) {
            float mt = fmaxf(fmaxf(s[rr][0], s[rr][1]), fmaxf(s[rr][2], s[rr][3]));
#pragma unroll
            for (int msk = 8; msk; msk >>= 1)
                mt = fmaxf(mt, __shfl_xor_sync(0xffffffffu, mt, msk));
            float mn = fmaxf(m[rr], mt);
            float corr = __expf((m[rr] - mn) * SCALE);
            float rs = 0.f;
#pragma unroll
            for (int cc = 0; cc < 4; cc++) {
                s[rr][cc] = __expf((s[rr][cc] - mn) * SCALE);
                rs += s[rr][cc];
            }
#pragma unroll
            for (int msk = 8; msk; msk >>= 1)
                rs += __shfl_xor_sync(0xffffffffu, rs, msk);
            l[rr] = l[rr] * corr + rs;
            m[rr] = mn;
            u64 c2 = dup2(corr);
            mul2(o2[rr][0], c2);
            mul2(o2[rr][1], c2);
        }

        // stage P into smem (vectorized over the 4 owned rows)
#pragma unroll
        for (int cc = 0; cc < 4; cc++)
            Ps[sw64(tx * 4 + cc, ty)] =
                make_float4(s[0][cc], s[1][cc], s[2][cc], s[3][cc]);
        __syncthreads();

        // O += P @ V — packed FFMA2
#pragma unroll 16
        for (int j = 0; j < 64; j++) {
            float4 a = Ps[sw64(j, ty)];
            ulonglong2 b = *(const ulonglong2*)(Vs + sw64(j, tx));
            u64 ar[4] = {dup2(a.x), dup2(a.y), dup2(a.z), dup2(a.w)};
#pragma unroll
            for (int rr = 0; rr < 4; rr++) {
                ffma2(o2[rr][0], ar[rr], b.x);
                ffma2(o2[rr][1], ar[rr], b.y);
            }
        }
    }

    // epilogue: normalize, store att, store row norms
    float* Ag = g_att[w];
#pragma unroll
    for (int rr = 0; rr < 4; rr++) {
        int row = rowblk + ty * 4 + rr;
        float inv = 1.f / l[rr];
        float2 p0 = unpk(o2[rr][0]), p1 = unpk(o2[rr][1]);
        float4 v = make_float4(p0.x * inv, p0.y * inv, p1.x * inv, p1.y * inv);
        *(float4*)(Ag + row * D + tx * 4) = v;
        float n = v.x * v.x + v.y * v.y + v.z * v.z + v.w * v.w;
#pragma unroll
        for (int msk = 8; msk; msk >>= 1)
            n += __shfl_xor_sync(0xffffffffu, n, msk);
        if (tx == 0) g_nrm[w][row] = n;
    }
}

// ---------------- 3) pairwise RBF: out[i][j] = exp(2*dot - nx - ny) --------
// 128x128 output tile per CTA, 256 threads, 8x8 microtile, packed FFMA2.
__global__ __launch_bounds__(256, 2)
void pair_kernel(float* __restrict__ out)
{
    extern __shared__ float4 sm[];
    float4* XA = sm;          // [k=64][32] chunks, swizzled
    float4* YA = sm + 2048;

    int tid = threadIdx.x;
    int tx = tid & 15, ty = tid >> 4;
    int i0 = blockIdx.x * 128, j0 = blockIdx.y * 128;
    const float* xa = g_att[0];
    const float* ya = g_att[1];

    for (int e = tid; e < 8192; e += 256) {
        int r = e >> 6, c = e & 63;
        ((float*)XA)[sw128(c, r >> 2) * 4 + (r & 3)] = xa[(i0 + r) * D + c];
        ((float*)YA)[sw128(c, r >> 2) * 4 + (r & 3)] = ya[(j0 + r) * D + c];
    }

    u64 acc2[8][4];           // [row][col-pair]
#pragma unroll
    for (int rr = 0; rr < 8; rr++)
#pragma unroll
        for (int p = 0; p < 4; p++) acc2[rr][p] = 0ull;
    __syncthreads();

#pragma unroll 8
    for (int k = 0; k < 64; k++) {
        float4 a0 = XA[sw128(k, ty)];
        float4 a1 = XA[sw128(k, 16 + ty)];
        ulonglong2 b0 = *(const ulonglong2*)(YA + sw128(k, tx));
        ulonglong2 b1 = *(const ulonglong2*)(YA + sw128(k, 16 + tx));
        u64 ar[8] = {dup2(a0.x), dup2(a0.y), dup2(a0.z), dup2(a0.w),
                     dup2(a1.x), dup2(a1.y), dup2(a1.z), dup2(a1.w)};
#pragma unroll
        for (int rr = 0; rr < 8; rr++) {
            ffma2(acc2[rr][0], ar[rr], b0.x);
            ffma2(acc2[rr][1], ar[rr], b0.y);
            ffma2(acc2[rr][2], ar[rr], b1.x);
            ffma2(acc2[rr][3], ar[rr], b1.y);
        }
    }

    float acc[8][8];
#pragma unroll
    for (int rr = 0; rr < 8; rr++)
#pragma unroll
        for (int p = 0; p < 4; p++) {
            float2 v = unpk(acc2[rr][p]);
            acc[rr][2 * p] = v.x; acc[rr][2 * p + 1] = v.y;
        }

    int ri[8], cj[8];
    float nx[8], ny[8];
#pragma unroll
    for (int q = 0; q < 8; q++) {
        ri[q] = i0 + ((q < 4) ? (ty * 4 + q) : (64 + ty * 4 + q - 4));
        cj[q] = j0 + ((q < 4) ? (tx * 4 + q) : (64 + tx * 4 + q - 4));
        nx[q] = g_nrm[0][ri[q]];
        ny[q] = g_nrm[1][cj[q]];
    }

#pragma unroll
    for (int rr = 0; rr < 8; rr++) {
        float4 v0 = make_float4(__expf(2.f * acc[rr][0] - nx[rr] - ny[0]),
                                __expf(2.f * acc[rr][1] - nx[rr] - ny[1]),
                                __expf(2.f * acc[rr][2] - nx[rr] - ny[2]),
                                __expf(2.f * acc[rr][3] - nx[rr] - ny[3]));
        float4 v1 = make_float4(__expf(2.f * acc[rr][4] - nx[rr] - ny[4]),
                                __expf(2.f * acc[rr][5] - nx[rr] - ny[5]),
                                __expf(2.f * acc[rr][6] - nx[rr] - ny[6]),
                                __expf(2.f * acc[rr][7] - nx[rr] - ny[7]));
        float* rowp = out + (size_t)ri[rr] * NPTS;
        *(float4*)(rowp + j0 + tx * 4) = v0;
        *(float4*)(rowp + j0 + 64 + tx * 4) = v1;
    }
}

// ---------------- launcher -------------------------------------------------
extern "C" void kernel_launch(void* const* d_in, const int* in_sizes, int n_in,
                              void* d_out, int out_size)
{
    const float* Wq = (const float*)d_in[0];   // rotation_params
    const float* Wk = (const float*)d_in[1];   // entangle_params
    const float* x  = (const float*)d_in[2];
    const float* y  = (const float*)d_in[3];
    float* out = (float*)d_out;

    cudaFuncSetAttribute(attn_kernel, cudaFuncAttributeMaxDynamicSharedMemorySize, 64 * 1024);
    cudaFuncSetAttribute(pair_kernel, cudaFuncAttributeMaxDynamicSharedMemorySize, 64 * 1024);

    proj_kernel<<<dim3(NPTS / 64, 2), dim3(64, 4)>>>(x, y, Wq, Wk);
    attn_kernel<<<dim3(NPTS / 64, 2), 256, 64 * 1024>>>(x, y);
    pair_kernel<<<dim3(NPTS / 128, NPTS / 128), 256, 64 * 1024>>>(out);
}

// round 9
// speedup vs baseline: 1.1435x; 1.0482x over previous
#include <cuda_runtime.h>
#include <cstdint>

#define NPTS 8192
#define D 64
#define C1 0.18033688011111793f   // 0.125 * log2(e)
#define PITCH 144                 // words per n-row in frag smem (144 % 32 == 16)

typedef unsigned long long u64;

// ---------------- scratch globals (static device memory; no runtime alloc) --
__device__ float g_q[2][NPTS * D];
__device__ float g_k[2][NPTS * D];
__device__ float g_vt[2][D * NPTS];      // inputs transposed [d][n]
__device__ float g_att[2][NPTS * D];
__device__ float g_nrm[2][NPTS];

// ---------------- packed fp32x2 helpers (pair kernel) ----------------------
__device__ __forceinline__ u64 dup2(float v) {
    u64 r; asm("mov.b64 %0, {%1, %1};" : "=l"(r) : "f"(v)); return r;
}
__device__ __forceinline__ void ffma2(u64& d, u64 a, u64 b) {
    asm("fma.rn.f32x2 %0, %1, %2, %0;" : "+l"(d) : "l"(a), "l"(b));
}
__device__ __forceinline__ float2 unpk(u64 v) {
    float lo, hi; asm("mov.b64 {%0, %1}, %2;" : "=f"(lo), "=f"(hi) : "l"(v));
    return make_float2(lo, hi);
}
__device__ __forceinline__ int sw128i(int k, int c4) { return k * 32 + (c4 ^ (k & 31)); }

// ---------------- tf32 mma helpers -----------------------------------------
__device__ __forceinline__ uint32_t tf32_of(float v) {
    uint32_t r; asm("cvt.rna.tf32.f32 %0, %1;" : "=r"(r) : "f"(v)); return r;
}
__device__ __forceinline__ float ex2(float x) {
    float r; asm("ex2.approx.f32 %0, %1;" : "=f"(r) : "f"(x)); return r;
}
__device__ __forceinline__ void mma8(float* d, const uint32_t* a, uint32_t b0, uint32_t b1) {
    asm volatile(
        "mma.sync.aligned.m16n8k8.row.col.f32.tf32.tf32.f32 "
        "{%0,%1,%2,%3}, {%4,%5,%6,%7}, {%8,%9}, {%0,%1,%2,%3};"
        : "+f"(d[0]), "+f"(d[1]), "+f"(d[2]), "+f"(d[3])
        : "r"(a[0]), "r"(a[1]), "r"(a[2]), "r"(a[3]), "r"(b0), "r"(b1));
}

// ---------------- 1) proj: Q/K fp32 + V^T fp32 -----------------------------
__global__ void proj_kernel(const float* __restrict__ x, const float* __restrict__ y,
                            const float* __restrict__ Wq, const float* __restrict__ Wk)
{
    __shared__ float wq[D * D], wk[D * D];
    __shared__ float xs[64][65];
    int tx = threadIdx.x, ty = threadIdx.y, tid = ty * 64 + tx;
    for (int i = tid; i < D * D; i += 256) { wq[i] = Wq[i]; wk[i] = Wk[i]; }
    int w = blockIdx.y;
    const float* in = w ? y : x;
    int row0 = blockIdx.x * 64;
    for (int e = tid; e < 64 * D; e += 256) xs[e >> 6][e & 63] = in[row0 * D + e];
    __syncthreads();

    for (int rl = ty; rl < 64; rl += 4) {
        float aq = 0.f, ak = 0.f;
#pragma unroll
        for (int k = 0; k < D; k++) {
            float v = xs[rl][k];
            aq = fmaf(v, wq[k * D + tx], aq);
            ak = fmaf(v, wk[k * D + tx], ak);
        }
        int idx = (row0 + rl) * D + tx;
        g_q[w][idx] = aq;
        g_k[w][idx] = ak;
    }
    // transposed raw input (V^T), coalesced writes over rows
    for (int e = tid; e < 64 * D; e += 256) {
        int d = e >> 6, r = e & 63;
        g_vt[w][d * NPTS + row0 + r] = xs[r][d];
    }
}

// ---------------- 2) mma.sync tf32 flash attention -------------------------
// 4 warps, BM=64 (16 rows/warp, full 64-col tiles), BN=64, 3xTF32 limbs.
__global__ __launch_bounds__(128, 2)
void attn_mma()
{
    extern __shared__ float smem[];
    float* Ks = smem;                 // [64][PITCH] interleaved {hi0,hi1,lo0,lo1}
    float* Vs = smem + 64 * PITCH;

    int tid = threadIdx.x;
    int lane = tid & 31, w4 = tid >> 5;
    int r = lane >> 2, c = lane & 3;
    int widx = blockIdx.y;
    int rowblk = blockIdx.x * 64;
    int R = rowblk + 16 * w4;

    const float* Qg = g_q[widx];
    const float* Kg = g_k[widx];
    const float* Vtg = g_vt[widx];

    // persistent Q fragments (2 limbs), a0..a3 = (r,c),(r+8,c),(r,c+4),(r+8,c+4)
    uint32_t qh[8][4], ql[8][4];
#pragma unroll
    for (int kk = 0; kk < 8; kk++)
#pragma unroll
        for (int i = 0; i < 4; i++) {
            int row = R + r + 8 * (i & 1);
            int col = kk * 8 + c + 4 * (i >> 1);
            float v = Qg[row * D + col];
            uint32_t hi = tf32_of(v);
            qh[kk][i] = hi;
            ql[kk][i] = tf32_of(v - __uint_as_float(hi));
        }

    float o[8][4];
#pragma unroll
    for (int nt = 0; nt < 8; nt++)
#pragma unroll
        for (int e = 0; e < 4; e++) o[nt][e] = 0.f;
    float m0 = -1e30f, m1 = -1e30f, l0 = 0.f, l1 = 0.f;

    for (int t = 0; t < NPTS / 64; t++) {
        int kb = t * 64;
        __syncthreads();   // previous tile's compute done before restaging

        // stage K tile: rows j (=n), cols d (=k) -> Ks[j][kk*16 + c*4 + {h,limb}]
        for (int e4 = tid; e4 < 1024; e4 += 128) {
            float4 kv = *(const float4*)(Kg + kb * D + e4 * 4);
            int j = e4 >> 4;
            int d0 = (e4 & 15) * 4;
            int kk = d0 >> 3, h = (d0 >> 2) & 1;
            int base = j * PITCH + kk * 16 + h;
            float vv[4] = {kv.x, kv.y, kv.z, kv.w};
#pragma unroll
            for (int i = 0; i < 4; i++) {
                uint32_t hi = tf32_of(vv[i]);
                Ks[base + i * 4]     = __uint_as_float(hi);
                Ks[base + i * 4 + 2] = __uint_as_float(tf32_of(vv[i] - __uint_as_float(hi)));
            }
        }
        // stage V tile: Vs[d][kk*16 + c*4 + {h,limb}] with k=j (seq dim)
        for (int e4 = tid; e4 < 1024; e4 += 128) {
            int d = e4 >> 4;
            int j0 = (e4 & 15) * 4;
            float4 vv4 = *(const float4*)(Vtg + d * NPTS + kb + j0);
            int kk = j0 >> 3, h = (j0 >> 2) & 1;
            int base = d * PITCH + kk * 16 + h;
            float vv[4] = {vv4.x, vv4.y, vv4.z, vv4.w};
#pragma unroll
            for (int i = 0; i < 4; i++) {
                uint32_t hi = tf32_of(vv[i]);
                Vs[base + i * 4]     = __uint_as_float(hi);
                Vs[base + i * 4 + 2] = __uint_as_float(tf32_of(vv[i] - __uint_as_float(hi)));
            }
        }
        __syncthreads();

        // ---- S = Q K^T (3xTF32) ----
        float s[8][4];
#pragma unroll
        for (int nt = 0; nt < 8; nt++)
#pragma unroll
            for (int e = 0; e < 4; e++) s[nt][e] = 0.f;

        int bbase = r * PITCH + c * 4;
#pragma unroll
        for (int kk = 0; kk < 8; kk++) {
            int kadd = kk * 16;
#pragma unroll
            for (int nt = 0; nt < 8; nt++) {
                float4 b = *(const float4*)(Ks + nt * (8 * PITCH) + bbase + kadd);
                uint32_t bh0 = __float_as_uint(b.x), bh1 = __float_as_uint(b.y);
                uint32_t bl0 = __float_as_uint(b.z), bl1 = __float_as_uint(b.w);
                mma8(s[nt], qh[kk], bh0, bh1);
                mma8(s[nt], ql[kk], bh0, bh1);
                mma8(s[nt], qh[kk], bl0, bl1);
            }
        }

        // ---- online softmax (rows r and r+8, replicated across quad) ----
        float mr0 = -1e30f, mr1 = -1e30f;
#pragma unroll
        for (int nt = 0; nt < 8; nt++) {
            mr0 = fmaxf(mr0, fmaxf(s[nt][0], s[nt][1]));
            mr1 = fmaxf(mr1, fmaxf(s[nt][2], s[nt][3]));
        }
        mr0 = fmaxf(mr0, __shfl_xor_sync(0xffffffffu, mr0, 1));
        mr0 = fmaxf(mr0, __shfl_xor_sync(0xffffffffu, mr0, 2));
        mr1 = fmaxf(mr1, __shfl_xor_sync(0xffffffffu, mr1, 1));
        mr1 = fmaxf(mr1, __shfl_xor_sync(0xffffffffu, mr1, 2));
        float mn0 = fmaxf(m0, mr0), mn1 = fmaxf(m1, mr1);
        float corr0 = ex2((m0 - mn0) * C1), corr1 = ex2((m1 - mn1) * C1);
        m0 = mn0; m1 = mn1;

        float sum0 = 0.f, sum1 = 0.f;
#pragma unroll
        for (int nt = 0; nt < 8; nt++) {
            s[nt][0] = ex2((s[nt][0] - mn0) * C1);
            s[nt][1] = ex2((s[nt][1] - mn0) * C1);
            s[nt][2] = ex2((s[nt][2] - mn1) * C1);
            s[nt][3] = ex2((s[nt][3] - mn1) * C1);
            sum0 += s[nt][0] + s[nt][1];
            sum1 += s[nt][2] + s[nt][3];
        }
        sum0 += __shfl_xor_sync(0xffffffffu, sum0, 1);
        sum0 += __shfl_xor_sync(0xffffffffu, sum0, 2);
        sum1 += __shfl_xor_sync(0xffffffffu, sum1, 1);
        sum1 += __shfl_xor_sync(0xffffffffu, sum1, 2);
        l0 = l0 * corr0 + sum0;
        l1 = l1 * corr1 + sum1;
#pragma unroll
        for (int nt = 0; nt < 8; nt++) {
            o[nt][0] *= corr0; o[nt][1] *= corr0;
            o[nt][2] *= corr1; o[nt][3] *= corr1;
        }

        // ---- O += P V (3xTF32); P stays warp-local via shuffles ----
        int srcA = (lane & ~3) | (c >> 1);
        int srcB = srcA + 2;
        bool odd = (c & 1) != 0;
#pragma unroll
        for (int kk = 0; kk < 8; kk++) {
            float v0a = __shfl_sync(0xffffffffu, s[kk][0], srcA);
            float v1a = __shfl_sync(0xffffffffu, s[kk][1], srcA);
            float v2a = __shfl_sync(0xffffffffu, s[kk][2], srcA);
            float v3a = __shfl_sync(0xffffffffu, s[kk][3], srcA);
            float v0b = __shfl_sync(0xffffffffu, s[kk][0], srcB);
            float v1b = __shfl_sync(0xffffffffu, s[kk][1], srcB);
            float v2b = __shfl_sync(0xffffffffu, s[kk][2], srcB);
            float v3b = __shfl_sync(0xffffffffu, s[kk][3], srcB);
            float af[4];
            af[0] = odd ? v1a : v0a;      // (r,     c)
            af[1] = odd ? v3a : v2a;      // (r+8,   c)
            af[2] = odd ? v1b : v0b;      // (r,   c+4)
            af[3] = odd ? v3b : v2b;      // (r+8, c+4)
            uint32_t ah[4], al[4];
#pragma unroll
            for (int i = 0; i < 4; i++) {
                ah[i] = tf32_of(af[i]);
                al[i] = tf32_of(af[i] - __uint_as_float(ah[i]));
            }
            int kadd = kk * 16;
#pragma unroll
            for (int nt = 0; nt < 8; nt++) {
                float4 b = *(const float4*)(Vs + nt * (8 * PITCH) + bbase + kadd);
                uint32_t bh0 = __float_as_uint(b.x), bh1 = __float_as_uint(b.y);
                uint32_t bl0 = __float_as_uint(b.z), bl1 = __float_as_uint(b.w);
                mma8(o[nt], ah, bh0, bh1);
                mma8(o[nt], al, bh0, bh1);
                mma8(o[nt], ah, bl0, bl1);
            }
        }
    }

    // ---- epilogue: normalize, store att + row norms ----
    float inv0 = 1.f / l0, inv1 = 1.f / l1;
    float* Ag = g_att[widx];
    int row0 = R + r, row1 = R + r + 8;
    float n0 = 0.f, n1 = 0.f;
#pragma unroll
    for (int nt = 0; nt < 8; nt++) {
        float2 v0 = make_float2(o[nt][0] * inv0, o[nt][1] * inv0);
        float2 v1 = make_float2(o[nt][2] * inv1, o[nt][3] * inv1);
        *(float2*)(Ag + row0 * D + nt * 8 + 2 * c) = v0;
        *(float2*)(Ag + row1 * D + nt * 8 + 2 * c) = v1;
        n0 += v0.x * v0.x + v0.y * v0.y;
        n1 += v1.x * v1.x + v1.y * v1.y;
    }
    n0 += __shfl_xor_sync(0xffffffffu, n0, 1);
    n0 += __shfl_xor_sync(0xffffffffu, n0, 2);
    n1 += __shfl_xor_sync(0xffffffffu, n1, 1);
    n1 += __shfl_xor_sync(0xffffffffu, n1, 2);
    if (c == 0) {
        g_nrm[widx][row0] = n0;
        g_nrm[widx][row1] = n1;
    }
}

// ---------------- 3) pairwise RBF (FFMA2, unchanged) -----------------------
__global__ __launch_bounds__(256, 2)
void pair_kernel(float* __restrict__ out)
{
    extern __shared__ float4 sm4[];
    float4* XA = sm4;
    float4* YA = sm4 + 2048;
    int tid = threadIdx.x;
    int tx = tid & 15, ty = tid >> 4;
    int i0 = blockIdx.x * 128, j0 = blockIdx.y * 128;
    const float* xa = g_att[0];
    const float* ya = g_att[1];

    for (int e = tid; e < 8192; e += 256) {
        int r = e >> 6, c = e & 63;
        ((float*)XA)[sw128i(c, r >> 2) * 4 + (r & 3)] = xa[(i0 + r) * D + c];
        ((float*)YA)[sw128i(c, r >> 2) * 4 + (r & 3)] = ya[(j0 + r) * D + c];
    }
    u64 acc2[8][4];
#pragma unroll
    for (int rr = 0; rr < 8; rr++)
#pragma unroll
        for (int p = 0; p < 4; p++) acc2[rr][p] = 0ull;
    __syncthreads();

#pragma unroll 8
    for (int k = 0; k < 64; k++) {
        float4 a0 = XA[sw128i(k, ty)];
        float4 a1 = XA[sw128i(k, 16 + ty)];
        ulonglong2 b0 = *(const ulonglong2*)(YA + sw128i(k, tx));
        ulonglong2 b1 = *(const ulonglong2*)(YA + sw128i(k, 16 + tx));
        u64 ar[8] = {dup2(a0.x), dup2(a0.y), dup2(a0.z), dup2(a0.w),
                     dup2(a1.x), dup2(a1.y), dup2(a1.z), dup2(a1.w)};
#pragma unroll
        for (int rr = 0; rr < 8; rr++) {
            ffma2(acc2[rr][0], ar[rr], b0.x);
            ffma2(acc2[rr][1], ar[rr], b0.y);
            ffma2(acc2[rr][2], ar[rr], b1.x);
            ffma2(acc2[rr][3], ar[rr], b1.y);
        }
    }
    float acc[8][8];
#pragma unroll
    for (int rr = 0; rr < 8; rr++)
#pragma unroll
        for (int p = 0; p < 4; p++) {
            float2 vv = unpk(acc2[rr][p]);
            acc[rr][2 * p] = vv.x; acc[rr][2 * p + 1] = vv.y;
        }
    int ri[8], cj[8];
    float nx[8], ny[8];
#pragma unroll
    for (int q = 0; q < 8; q++) {
        ri[q] = i0 + ((q < 4) ? (ty * 4 + q) : (64 + ty * 4 + q - 4));
        cj[q] = j0 + ((q < 4) ? (tx * 4 + q) : (64 + tx * 4 + q - 4));
        nx[q] = g_nrm[0][ri[q]];
        ny[q] = g_nrm[1][cj[q]];
    }
#pragma unroll
    for (int rr = 0; rr < 8; rr++) {
        float4 v0 = make_float4(__expf(2.f * acc[rr][0] - nx[rr] - ny[0]),
                                __expf(2.f * acc[rr][1] - nx[rr] - ny[1]),
                                __expf(2.f * acc[rr][2] - nx[rr] - ny[2]),
                                __expf(2.f * acc[rr][3] - nx[rr] - ny[3]));
        float4 v1 = make_float4(__expf(2.f * acc[rr][4] - nx[rr] - ny[4]),
                                __expf(2.f * acc[rr][5] - nx[rr] - ny[5]),
                                __expf(2.f * acc[rr][6] - nx[rr] - ny[6]),
                                __expf(2.f * acc[rr][7] - nx[rr] - ny[7]));
        float* rowp = out + (size_t)ri[rr] * NPTS;
        *(float4*)(rowp + j0 + tx * 4) = v0;
        *(float4*)(rowp + j0 + 64 + tx * 4) = v1;
    }
}

// ---------------- launcher -------------------------------------------------
extern "C" void kernel_launch(void* const* d_in, const int* in_sizes, int n_in,
                              void* d_out, int out_size)
{
    const float* Wq = (const float*)d_in[0];
    const float* Wk = (const float*)d_in[1];
    const float* x  = (const float*)d_in[2];
    const float* y  = (const float*)d_in[3];
    float* out = (float*)d_out;

    const int attn_smem = 2 * 64 * PITCH * sizeof(float);   // 73728 B
    cudaFuncSetAttribute(attn_mma, cudaFuncAttributeMaxDynamicSharedMemorySize, attn_smem);
    cudaFuncSetAttribute(pair_kernel, cudaFuncAttributeMaxDynamicSharedMemorySize, 64 * 1024);

    proj_kernel<<<dim3(NPTS / 64, 2), dim3(64, 4)>>>(x, y, Wq, Wk);
    attn_mma<<<dim3(NPTS / 64, 2), 128, attn_smem>>>();
    pair_kernel<<<dim3(NPTS / 128, NPTS / 128), 256, 64 * 1024>>>(out);
}

// round 11
// speedup vs baseline: 1.7014x; 1.4878x over previous
#include <cuda_runtime.h>
#include <cstdint>

#define NPTS 8192
#define D 64
#define C1 0.18033688011111793f   // 0.125 * log2(e)
#define KPITCH 104                // words/row: 3 regions of 32 + 8 pad (mod 32 == 8)
#define VPITCH 72                 // words/row: 2 regions of 32 + 8 pad (mod 32 == 8)

typedef unsigned long long u64;

// ---------------- scratch globals ------------------------------------------
__device__ float g_q[2][NPTS * D];
__device__ float g_k[2][NPTS * D];
__device__ float g_vt[2][D * NPTS];                       // inputs transposed [d][n]
__device__ __align__(16) uint32_t g_kb[2][NPTS][KPITCH];  // K bf16 3-limb, frag-ready
__device__ __align__(16) uint32_t g_vb[2][NPTS / 64][D][VPITCH]; // V^T bf16 2-limb
__device__ float g_att[2][NPTS * D];
__device__ float g_nrm[2][NPTS];

// ---------------- packed fp32x2 helpers (pair kernel) ----------------------
__device__ __forceinline__ u64 dup2(float v) {
    u64 r; asm("mov.b64 %0, {%1, %1};" : "=l"(r) : "f"(v)); return r;
}
__device__ __forceinline__ void ffma2(u64& d, u64 a, u64 b) {
    asm("fma.rn.f32x2 %0, %1, %2, %0;" : "+l"(d) : "l"(a), "l"(b));
}
__device__ __forceinline__ float2 unpk(u64 v) {
    float lo, hi; asm("mov.b64 {%0, %1}, %2;" : "=f"(lo), "=f"(hi) : "l"(v));
    return make_float2(lo, hi);
}
__device__ __forceinline__ int sw128i(int k, int c4) { return k * 32 + (c4 ^ (k & 31)); }

// ---------------- bf16 mma helpers -----------------------------------------
__device__ __forceinline__ uint32_t pack2(float lo, float hi) {
    uint32_t d; asm("cvt.rn.bf16x2.f32 %0, %1, %2;" : "=r"(d) : "f"(hi), "f"(lo));
    return d;
}
__device__ __forceinline__ float lowf(uint32_t w)  { return __uint_as_float(w << 16); }
__device__ __forceinline__ float highf(uint32_t w) { return __uint_as_float(w & 0xffff0000u); }
__device__ __forceinline__ float ex2(float x) {
    float r; asm("ex2.approx.f32 %0, %1;" : "=f"(r) : "f"(x)); return r;
}
__device__ __forceinline__ void mmab(float* d, const uint32_t* a, uint32_t b0, uint32_t b1) {
    asm volatile(
        "mma.sync.aligned.m16n8k16.row.col.f32.bf16.bf16.f32 "
        "{%0,%1,%2,%3},{%4,%5,%6,%7},{%8,%9},{%0,%1,%2,%3};"
        : "+f"(d[0]), "+f"(d[1]), "+f"(d[2]), "+f"(d[3])
        : "r"(a[0]), "r"(a[1]), "r"(a[2]), "r"(a[3]), "r"(b0), "r"(b1));
}
// interleaved position for pair-index p: (b0,b1) of fragments land adjacent
__device__ __forceinline__ int ppos(int p) {
    int kc = p >> 3, q = p & 7;
    return kc * 8 + ((q < 4) ? 2 * q : 2 * q - 7);
}

// ---------------- 1) proj: Q/K fp32 + V^T fp32 -----------------------------
__global__ void proj_kernel(const float* __restrict__ x, const float* __restrict__ y,
                            const float* __restrict__ Wq, const float* __restrict__ Wk)
{
    __shared__ float wq[D * D], wk[D * D];
    __shared__ float xs[64][65];
    int tx = threadIdx.x, ty = threadIdx.y, tid = ty * 64 + tx;
    for (int i = tid; i < D * D; i += 256) { wq[i] = Wq[i]; wk[i] = Wk[i]; }
    int w = blockIdx.y;
    const float* in = w ? y : x;
    int row0 = blockIdx.x * 64;
    for (int e = tid; e < 64 * D; e += 256) xs[e >> 6][e & 63] = in[row0 * D + e];
    __syncthreads();

    for (int rl = ty; rl < 64; rl += 4) {
        float aq = 0.f, ak = 0.f;
#pragma unroll
        for (int k = 0; k < D; k++) {
            float v = xs[rl][k];
            aq = fmaf(v, wq[k * D + tx], aq);
            ak = fmaf(v, wk[k * D + tx], ak);
        }
        int idx = (row0 + rl) * D + tx;
        g_q[w][idx] = aq;
        g_k[w][idx] = ak;
    }
    for (int e = tid; e < 64 * D; e += 256) {
        int d = e >> 6, r = e & 63;
        g_vt[w][d * NPTS + row0 + r] = xs[r][d];
    }
}

// ---------------- 1b) pack K (3-limb) and V^T (2-limb) into bf16x2 ---------
__global__ void pack_kernel()
{
    int w = blockIdx.y;
    int idx = blockIdx.x * 256 + threadIdx.x;
    if (idx < NPTS * 32) {               // K: (j, pair p)
        int j = idx >> 5, p = idx & 31;
        float2 v = *(const float2*)(g_k[w] + j * D + 2 * p);
        uint32_t h = pack2(v.x, v.y);
        float r0 = v.x - lowf(h), r1 = v.y - highf(h);
        uint32_t m = pack2(r0, r1);
        r0 -= lowf(m); r1 -= highf(m);
        uint32_t l = pack2(r0, r1);
        int pos = ppos(p);
        g_kb[w][j][pos]      = h;
        g_kb[w][j][32 + pos] = m;
        g_kb[w][j][64 + pos] = l;
    } else {                             // V: (tile t, d, pair p)
        int i2 = idx - NPTS * 32;
        int t = i2 >> 11, d = (i2 >> 5) & 63, p = i2 & 31;
        float2 v = *(const float2*)(g_vt[w] + d * NPTS + t * 64 + 2 * p);
        uint32_t h = pack2(v.x, v.y);
        float r0 = v.x - lowf(h), r1 = v.y - highf(h);
        uint32_t l = pack2(r0, r1);
        int pos = ppos(p);
        g_vb[w][t][d][pos]      = h;
        g_vb[w][t][d][32 + pos] = l;
    }
}

// ---------------- 2) bf16 mma.sync flash attention -------------------------
// 4 warps, BM=64 (16 rows/warp), BN=64. QK: 3-limb 6-mma; PV: 2-limb 3-mma.
__global__ __launch_bounds__(128, 2)
void attn_mma()
{
    extern __shared__ uint32_t smw[];
    uint32_t* Ks = smw;                 // [64][KPITCH]
    uint32_t* Vs = smw + 64 * KPITCH;   // [64][VPITCH]

    int tid = threadIdx.x;
    int lane = tid & 31, w4 = tid >> 5;
    int r = lane >> 2, c = lane & 3;
    int widx = blockIdx.y;
    int R = blockIdx.x * 64 + 16 * w4;

    const float* Qg = g_q[widx];

    // persistent Q fragments: 3 limbs x 4 k-chunks x 4 regs
    uint32_t qh[4][4], qm[4][4], ql[4][4];
#pragma unroll
    for (int kc = 0; kc < 4; kc++)
#pragma unroll
        for (int i = 0; i < 4; i++) {
            int row = R + r + 8 * (i & 1);
            int col = kc * 16 + 2 * c + 8 * (i >> 1);
            float2 q2 = *(const float2*)(Qg + row * D + col);
            uint32_t h = pack2(q2.x, q2.y);
            float r0 = q2.x - lowf(h), r1 = q2.y - highf(h);
            uint32_t m = pack2(r0, r1);
            r0 -= lowf(m); r1 -= highf(m);
            qh[kc][i] = h; qm[kc][i] = m; ql[kc][i] = pack2(r0, r1);
        }

    float o[8][4];
#pragma unroll
    for (int nt = 0; nt < 8; nt++)
#pragma unroll
        for (int e = 0; e < 4; e++) o[nt][e] = 0.f;
    float m0 = -1e30f, m1 = -1e30f, l0 = 0.f, l1 = 0.f;

    int bofs = r * KPITCH + 2 * c;
    int vofs = r * VPITCH + 2 * c;

    for (int t = 0; t < NPTS / 64; t++) {
        __syncthreads();   // previous tile's reads done before restaging
        // stage K tile (flat copy; global layout == smem layout)
        {
            const uint4* src = (const uint4*)(&g_kb[widx][t * 64][0]);
            uint4* dst = (uint4*)Ks;
            for (int i = tid; i < 64 * (KPITCH / 4); i += 128) dst[i] = src[i];
            const uint4* srcv = (const uint4*)(&g_vb[widx][t][0][0]);
            uint4* dstv = (uint4*)Vs;
            for (int i = tid; i < 64 * (VPITCH / 4); i += 128) dstv[i] = srcv[i];
        }
        __syncthreads();

        // ---- S = Q K^T (3-limb bf16, 6 products) ----
        float s[8][4];
#pragma unroll
        for (int nt = 0; nt < 8; nt++)
#pragma unroll
            for (int e = 0; e < 4; e++) s[nt][e] = 0.f;

#pragma unroll
        for (int kc = 0; kc < 4; kc++) {
#pragma unroll
            for (int nt = 0; nt < 8; nt++) {
                const uint32_t* rp = Ks + nt * 8 * KPITCH + bofs + kc * 8;
                uint2 bh = *(const uint2*)(rp);
                uint2 bm = *(const uint2*)(rp + 32);
                uint2 bl = *(const uint2*)(rp + 64);
                mmab(s[nt], qh[kc], bh.x, bh.y);
                mmab(s[nt], qm[kc], bh.x, bh.y);
                mmab(s[nt], qh[kc], bm.x, bm.y);
                mmab(s[nt], qm[kc], bm.x, bm.y);
                mmab(s[nt], qh[kc], bl.x, bl.y);
                mmab(s[nt], ql[kc], bh.x, bh.y);
            }
        }

        // ---- online softmax (rows r, r+8; quad-replicated) ----
        float mr0 = -1e30f, mr1 = -1e30f;
#pragma unroll
        for (int nt = 0; nt < 8; nt++) {
            mr0 = fmaxf(mr0, fmaxf(s[nt][0], s[nt][1]));
            mr1 = fmaxf(mr1, fmaxf(s[nt][2], s[nt][3]));
        }
        mr0 = fmaxf(mr0, __shfl_xor_sync(0xffffffffu, mr0, 1));
        mr0 = fmaxf(mr0, __shfl_xor_sync(0xffffffffu, mr0, 2));
        mr1 = fmaxf(mr1, __shfl_xor_sync(0xffffffffu, mr1, 1));
        mr1 = fmaxf(mr1, __shfl_xor_sync(0xffffffffu, mr1, 2));
        float mn0 = fmaxf(m0, mr0), mn1 = fmaxf(m1, mr1);
        float corr0 = ex2((m0 - mn0) * C1), corr1 = ex2((m1 - mn1) * C1);
        m0 = mn0; m1 = mn1;

        float sum0 = 0.f, sum1 = 0.f;
#pragma unroll
        for (int nt = 0; nt < 8; nt++) {
            s[nt][0] = ex2((s[nt][0] - mn0) * C1);
            s[nt][1] = ex2((s[nt][1] - mn0) * C1);
            s[nt][2] = ex2((s[nt][2] - mn1) * C1);
            s[nt][3] = ex2((s[nt][3] - mn1) * C1);
            sum0 += s[nt][0] + s[nt][1];
            sum1 += s[nt][2] + s[nt][3];
        }
        sum0 += __shfl_xor_sync(0xffffffffu, sum0, 1);
        sum0 += __shfl_xor_sync(0xffffffffu, sum0, 2);
        sum1 += __shfl_xor_sync(0xffffffffu, sum1, 1);
        sum1 += __shfl_xor_sync(0xffffffffu, sum1, 2);
        l0 = l0 * corr0 + sum0;
        l1 = l1 * corr1 + sum1;
#pragma unroll
        for (int nt = 0; nt < 8; nt++) {
            o[nt][0] *= corr0; o[nt][1] *= corr0;
            o[nt][2] *= corr1; o[nt][3] *= corr1;
        }

        // ---- O += P V (2-limb bf16, 3 products); P fragments are LOCAL ----
#pragma unroll
        for (int kc = 0; kc < 4; kc++) {
            uint32_t ah[4], al[4];
#pragma unroll
            for (int i = 0; i < 4; i++) {
                // a0,a1 from s[2kc] (rows r / r+8); a2,a3 from s[2kc+1]
                float va = (i & 2) ? s[2 * kc + 1][(i & 1) * 2]
                                   : s[2 * kc][(i & 1) * 2];
                float vb = (i & 2) ? s[2 * kc + 1][(i & 1) * 2 + 1]
                                   : s[2 * kc][(i & 1) * 2 + 1];
                uint32_t h = pack2(va, vb);
                ah[i] = h;
                al[i] = pack2(va - lowf(h), vb - highf(h));
            }
#pragma unroll
            for (int nt = 0; nt < 8; nt++) {
                const uint32_t* rp = Vs + nt * 8 * VPITCH + vofs + kc * 8;
                uint2 vh = *(const uint2*)(rp);
                uint2 vl = *(const uint2*)(rp + 32);
                mmab(o[nt], ah, vh.x, vh.y);
                mmab(o[nt], al, vh.x, vh.y);
                mmab(o[nt], ah, vl.x, vl.y);
            }
        }
    }

    // ---- epilogue: normalize, store att + row norms ----
    float inv0 = 1.f / l0, inv1 = 1.f / l1;
    float* Ag = g_att[widx];
    int row0 = R + r, row1 = R + r + 8;
    float n0 = 0.f, n1 = 0.f;
#pragma unroll
    for (int nt = 0; nt < 8; nt++) {
        float2 v0 = make_float2(o[nt][0] * inv0, o[nt][1] * inv0);
        float2 v1 = make_float2(o[nt][2] * inv1, o[nt][3] * inv1);
        *(float2*)(Ag + row0 * D + nt * 8 + 2 * c) = v0;
        *(float2*)(Ag + row1 * D + nt * 8 + 2 * c) = v1;
        n0 += v0.x * v0.x + v0.y * v0.y;
        n1 += v1.x * v1.x + v1.y * v1.y;
    }
    n0 += __shfl_xor_sync(0xffffffffu, n0, 1);
    n0 += __shfl_xor_sync(0xffffffffu, n0, 2);
    n1 += __shfl_xor_sync(0xffffffffu, n1, 1);
    n1 += __shfl_xor_sync(0xffffffffu, n1, 2);
    if (c == 0) {
        g_nrm[widx][row0] = n0;
        g_nrm[widx][row1] = n1;
    }
}

// ---------------- 3) pairwise RBF (FFMA2, unchanged) -----------------------
__global__ __launch_bounds__(256, 2)
void pair_kernel(float* __restrict__ out)
{
    extern __shared__ float4 sm4[];
    float4* XA = sm4;
    float4* YA = sm4 + 2048;
    int tid = threadIdx.x;
    int tx = tid & 15, ty = tid >> 4;
    int i0 = blockIdx.x * 128, j0 = blockIdx.y * 128;
    const float* xa = g_att[0];
    const float* ya = g_att[1];

    for (int e = tid; e < 8192; e += 256) {
        int r = e >> 6, c = e & 63;
        ((float*)XA)[sw128i(c, r >> 2) * 4 + (r & 3)] = xa[(i0 + r) * D + c];
        ((float*)YA)[sw128i(c, r >> 2) * 4 + (r & 3)] = ya[(j0 + r) * D + c];
    }
    u64 acc2[8][4];
#pragma unroll
    for (int rr = 0; rr < 8; rr++)
#pragma unroll
        for (int p = 0; p < 4; p++) acc2[rr][p] = 0ull;
    __syncthreads();

#pragma unroll 8
    for (int k = 0; k < 64; k++) {
        float4 a0 = XA[sw128i(k, ty)];
        float4 a1 = XA[sw128i(k, 16 + ty)];
        ulonglong2 b0 = *(const ulonglong2*)(YA + sw128i(k, tx));
        ulonglong2 b1 = *(const ulonglong2*)(YA + sw128i(k, 16 + tx));
        u64 ar[8] = {dup2(a0.x), dup2(a0.y), dup2(a0.z), dup2(a0.w),
                     dup2(a1.x), dup2(a1.y), dup2(a1.z), dup2(a1.w)};
#pragma unroll
        for (int rr = 0; rr < 8; rr++) {
            ffma2(acc2[rr][0], ar[rr], b0.x);
            ffma2(acc2[rr][1], ar[rr], b0.y);
            ffma2(acc2[rr][2], ar[rr], b1.x);
            ffma2(acc2[rr][3], ar[rr], b1.y);
        }
    }
    float acc[8][8];
#pragma unroll
    for (int rr = 0; rr < 8; rr++)
#pragma unroll
        for (int p = 0; p < 4; p++) {
            float2 vv = unpk(acc2[rr][p]);
            acc[rr][2 * p] = vv.x; acc[rr][2 * p + 1] = vv.y;
        }
    int ri[8];
    float nx[8], ny[8];
#pragma unroll
    for (int q = 0; q < 8; q++) {
        ri[q] = i0 + ((q < 4) ? (ty * 4 + q) : (64 + ty * 4 + q - 4));
        int cjq = j0 + ((q < 4) ? (tx * 4 + q) : (64 + tx * 4 + q - 4));
        nx[q] = g_nrm[0][ri[q]];
        ny[q] = g_nrm[1][cjq];
    }
#pragma unroll
    for (int rr = 0; rr < 8; rr++) {
        float4 v0 = make_float4(__expf(2.f * acc[rr][0] - nx[rr] - ny[0]),
                                __expf(2.f * acc[rr][1] - nx[rr] - ny[1]),
                                __expf(2.f * acc[rr][2] - nx[rr] - ny[2]),
                                __expf(2.f * acc[rr][3] - nx[rr] - ny[3]));
        float4 v1 = make_float4(__expf(2.f * acc[rr][4] - nx[rr] - ny[4]),
                                __expf(2.f * acc[rr][5] - nx[rr] - ny[5]),
                                __expf(2.f * acc[rr][6] - nx[rr] - ny[6]),
                                __expf(2.f * acc[rr][7] - nx[rr] - ny[7]));
        float* rowp = out + (size_t)ri[rr] * NPTS;
        *(float4*)(rowp + j0 + tx * 4) = v0;
        *(float4*)(rowp + j0 + 64 + tx * 4) = v1;
    }
}

// ---------------- launcher -------------------------------------------------
extern "C" void kernel_launch(void* const* d_in, const int* in_sizes, int n_in,
                              void* d_out, int out_size)
{
    const float* Wq = (const float*)d_in[0];
    const float* Wk = (const float*)d_in[1];
    const float* x  = (const float*)d_in[2];
    const float* y  = (const float*)d_in[3];
    float* out = (float*)d_out;

    const int attn_smem = (64 * KPITCH + 64 * VPITCH) * 4;   // 45056 B
    cudaFuncSetAttribute(attn_mma, cudaFuncAttributeMaxDynamicSharedMemorySize, attn_smem);
    cudaFuncSetAttribute(pair_kernel, cudaFuncAttributeMaxDynamicSharedMemorySize, 64 * 1024);

    proj_kernel<<<dim3(NPTS / 64, 2), dim3(64, 4)>>>(x, y, Wq, Wk);
    pack_kernel<<<dim3((NPTS * 32 + NPTS * 32) / 256, 2), 256>>>();
    attn_mma<<<dim3(NPTS / 64, 2), 128, attn_smem>>>();
    pair_kernel<<<dim3(NPTS / 128, NPTS / 128), 256, 64 * 1024>>>(out);
}

// round 12
// speedup vs baseline: 1.9692x; 1.1574x over previous
#include <cuda_runtime.h>
#include <cstdint>

#define NPTS 8192
#define D 64
#define C1 0.18033688011111793f   // 0.125 * log2(e)
#define KPITCH 72                 // words/row: 2 regions of 32 + 8 pad (mod 32 == 8)
#define VPITCH 72

typedef unsigned long long u64;

// ---------------- scratch globals ------------------------------------------
__device__ float g_q[2][NPTS * D];
__device__ float g_k[2][NPTS * D];
__device__ float g_vt[2][D * NPTS];                       // inputs transposed [d][n]
__device__ __align__(16) uint32_t g_kb[2][NPTS][KPITCH];  // K bf16 2-limb, frag-ready
__device__ __align__(16) uint32_t g_vb[2][NPTS / 64][D][VPITCH]; // V^T bf16 2-limb
__device__ float g_att[2][NPTS * D];
__device__ float g_nrm[2][NPTS];

// ---------------- packed fp32x2 helpers (pair kernel) ----------------------
__device__ __forceinline__ u64 dup2(float v) {
    u64 r; asm("mov.b64 %0, {%1, %1};" : "=l"(r) : "f"(v)); return r;
}
__device__ __forceinline__ void ffma2(u64& d, u64 a, u64 b) {
    asm("fma.rn.f32x2 %0, %1, %2, %0;" : "+l"(d) : "l"(a), "l"(b));
}
__device__ __forceinline__ float2 unpk(u64 v) {
    float lo, hi; asm("mov.b64 {%0, %1}, %2;" : "=f"(lo), "=f"(hi) : "l"(v));
    return make_float2(lo, hi);
}
__device__ __forceinline__ int sw128i(int k, int c4) { return k * 32 + (c4 ^ (k & 31)); }

// ---------------- bf16 mma helpers -----------------------------------------
__device__ __forceinline__ uint32_t pack2(float lo, float hi) {
    uint32_t d; asm("cvt.rn.bf16x2.f32 %0, %1, %2;" : "=r"(d) : "f"(hi), "f"(lo));
    return d;
}
__device__ __forceinline__ float lowf(uint32_t w)  { return __uint_as_float(w << 16); }
__device__ __forceinline__ float highf(uint32_t w) { return __uint_as_float(w & 0xffff0000u); }
__device__ __forceinline__ float ex2(float x) {
    float r; asm("ex2.approx.f32 %0, %1;" : "=f"(r) : "f"(x)); return r;
}
__device__ __forceinline__ void mmab(float* d, const uint32_t* a, uint32_t b0, uint32_t b1) {
    asm volatile(
        "mma.sync.aligned.m16n8k16.row.col.f32.bf16.bf16.f32 "
        "{%0,%1,%2,%3},{%4,%5,%6,%7},{%8,%9},{%0,%1,%2,%3};"
        : "+f"(d[0]), "+f"(d[1]), "+f"(d[2]), "+f"(d[3])
        : "r"(a[0]), "r"(a[1]), "r"(a[2]), "r"(a[3]), "r"(b0), "r"(b1));
}
// interleaved position for pair-index p: (b0,b1) of fragments land adjacent
__device__ __forceinline__ int ppos(int p) {
    int kc = p >> 3, q = p & 7;
    return kc * 8 + ((q < 4) ? 2 * q : 2 * q - 7);
}

// ---------------- 1) proj: Q/K fp32 + V^T fp32 -----------------------------
__global__ void proj_kernel(const float* __restrict__ x, const float* __restrict__ y,
                            const float* __restrict__ Wq, const float* __restrict__ Wk)
{
    __shared__ float wq[D * D], wk[D * D];
    __shared__ float xs[64][65];
    int tx = threadIdx.x, ty = threadIdx.y, tid = ty * 64 + tx;
    for (int i = tid; i < D * D; i += 256) { wq[i] = Wq[i]; wk[i] = Wk[i]; }
    int w = blockIdx.y;
    const float* in = w ? y : x;
    int row0 = blockIdx.x * 64;
    for (int e = tid; e < 64 * D; e += 256) xs[e >> 6][e & 63] = in[row0 * D + e];
    __syncthreads();

    for (int rl = ty; rl < 64; rl += 4) {
        float aq = 0.f, ak = 0.f;
#pragma unroll
        for (int k = 0; k < D; k++) {
            float v = xs[rl][k];
            aq = fmaf(v, wq[k * D + tx], aq);
            ak = fmaf(v, wk[k * D + tx], ak);
        }
        int idx = (row0 + rl) * D + tx;
        g_q[w][idx] = aq;
        g_k[w][idx] = ak;
    }
    for (int e = tid; e < 64 * D; e += 256) {
        int d = e >> 6, r = e & 63;
        g_vt[w][d * NPTS + row0 + r] = xs[r][d];
    }
}

// ---------------- 1b) pack K (2-limb) and V^T (2-limb) into bf16x2 ---------
__global__ void pack_kernel()
{
    int w = blockIdx.y;
    int idx = blockIdx.x * 256 + threadIdx.x;
    if (idx < NPTS * 32) {               // K: (j, pair p)
        int j = idx >> 5, p = idx & 31;
        float2 v = *(const float2*)(g_k[w] + j * D + 2 * p);
        uint32_t h = pack2(v.x, v.y);
        float r0 = v.x - lowf(h), r1 = v.y - highf(h);
        uint32_t m = pack2(r0, r1);
        int pos = ppos(p);
        g_kb[w][j][pos]      = h;
        g_kb[w][j][32 + pos] = m;
    } else {                             // V: (tile t, d, pair p)
        int i2 = idx - NPTS * 32;
        int t = i2 >> 11, d = (i2 >> 5) & 63, p = i2 & 31;
        float2 v = *(const float2*)(g_vt[w] + d * NPTS + t * 64 + 2 * p);
        uint32_t h = pack2(v.x, v.y);
        float r0 = v.x - lowf(h), r1 = v.y - highf(h);
        uint32_t l = pack2(r0, r1);
        int pos = ppos(p);
        g_vb[w][t][d][pos]      = h;
        g_vb[w][t][d][32 + pos] = l;
    }
}

// ---------------- 2) bf16 mma.sync flash attention -------------------------
// 4 warps, BM=64 (16 rows/warp), BN=64. QK: 2-limb 3-mma; PV: 2-limb 3-mma.
__global__ __launch_bounds__(128, 2)
void attn_mma()
{
    extern __shared__ uint32_t smw[];
    uint32_t* Ks = smw;                 // [64][KPITCH]
    uint32_t* Vs = smw + 64 * KPITCH;   // [64][VPITCH]

    int tid = threadIdx.x;
    int lane = tid & 31, w4 = tid >> 5;
    int r = lane >> 2, c = lane & 3;
    int widx = blockIdx.y;
    int R = blockIdx.x * 64 + 16 * w4;

    const float* Qg = g_q[widx];

    // persistent Q fragments: 2 limbs x 4 k-chunks x 4 regs
    uint32_t qh[4][4], qm[4][4];
#pragma unroll
    for (int kc = 0; kc < 4; kc++)
#pragma unroll
        for (int i = 0; i < 4; i++) {
            int row = R + r + 8 * (i & 1);
            int col = kc * 16 + 2 * c + 8 * (i >> 1);
            float2 q2 = *(const float2*)(Qg + row * D + col);
            uint32_t h = pack2(q2.x, q2.y);
            float r0 = q2.x - lowf(h), r1 = q2.y - highf(h);
            qh[kc][i] = h; qm[kc][i] = pack2(r0, r1);
        }

    float o[8][4];
#pragma unroll
    for (int nt = 0; nt < 8; nt++)
#pragma unroll
        for (int e = 0; e < 4; e++) o[nt][e] = 0.f;
    float m0 = -1e30f, m1 = -1e30f, l0 = 0.f, l1 = 0.f;

    int bofs = r * KPITCH + 2 * c;
    int vofs = r * VPITCH + 2 * c;

    for (int t = 0; t < NPTS / 64; t++) {
        __syncthreads();   // previous tile's reads done before restaging
        // stage K/V tiles (flat copy; global layout == smem layout)
        {
            const uint4* src = (const uint4*)(&g_kb[widx][t * 64][0]);
            uint4* dst = (uint4*)Ks;
            for (int i = tid; i < 64 * (KPITCH / 4); i += 128) dst[i] = src[i];
            const uint4* srcv = (const uint4*)(&g_vb[widx][t][0][0]);
            uint4* dstv = (uint4*)Vs;
            for (int i = tid; i < 64 * (VPITCH / 4); i += 128) dstv[i] = srcv[i];
        }
        __syncthreads();

        // ---- S = Q K^T (2-limb bf16, 3 products) ----
        float s[8][4];
#pragma unroll
        for (int nt = 0; nt < 8; nt++)
#pragma unroll
            for (int e = 0; e < 4; e++) s[nt][e] = 0.f;

#pragma unroll
        for (int kc = 0; kc < 4; kc++) {
#pragma unroll
            for (int nt = 0; nt < 8; nt++) {
                const uint32_t* rp = Ks + nt * 8 * KPITCH + bofs + kc * 8;
                uint2 bh = *(const uint2*)(rp);
                uint2 bm = *(const uint2*)(rp + 32);
                mmab(s[nt], qh[kc], bh.x, bh.y);
                mmab(s[nt], qm[kc], bh.x, bh.y);
                mmab(s[nt], qh[kc], bm.x, bm.y);
            }
        }

        // ---- online softmax (rows r, r+8; quad-replicated) ----
        float mr0 = -1e30f, mr1 = -1e30f;
#pragma unroll
        for (int nt = 0; nt < 8; nt++) {
            mr0 = fmaxf(mr0, fmaxf(s[nt][0], s[nt][1]));
            mr1 = fmaxf(mr1, fmaxf(s[nt][2], s[nt][3]));
        }
        mr0 = fmaxf(mr0, __shfl_xor_sync(0xffffffffu, mr0, 1));
        mr0 = fmaxf(mr0, __shfl_xor_sync(0xffffffffu, mr0, 2));
        mr1 = fmaxf(mr1, __shfl_xor_sync(0xffffffffu, mr1, 1));
        mr1 = fmaxf(mr1, __shfl_xor_sync(0xffffffffu, mr1, 2));
        float mn0 = fmaxf(m0, mr0), mn1 = fmaxf(m1, mr1);
        float corr0 = ex2((m0 - mn0) * C1), corr1 = ex2((m1 - mn1) * C1);
        m0 = mn0; m1 = mn1;

        float sum0 = 0.f, sum1 = 0.f;
#pragma unroll
        for (int nt = 0; nt < 8; nt++) {
            s[nt][0] = ex2((s[nt][0] - mn0) * C1);
            s[nt][1] = ex2((s[nt][1] - mn0) * C1);
            s[nt][2] = ex2((s[nt][2] - mn1) * C1);
            s[nt][3] = ex2((s[nt][3] - mn1) * C1);
            sum0 += s[nt][0] + s[nt][1];
            sum1 += s[nt][2] + s[nt][3];
        }
        sum0 += __shfl_xor_sync(0xffffffffu, sum0, 1);
        sum0 += __shfl_xor_sync(0xffffffffu, sum0, 2);
        sum1 += __shfl_xor_sync(0xffffffffu, sum1, 1);
        sum1 += __shfl_xor_sync(0xffffffffu, sum1, 2);
        l0 = l0 * corr0 + sum0;
        l1 = l1 * corr1 + sum1;
#pragma unroll
        for (int nt = 0; nt < 8; nt++) {
            o[nt][0] *= corr0; o[nt][1] *= corr0;
            o[nt][2] *= corr1; o[nt][3] *= corr1;
        }

        // ---- O += P V (2-limb bf16, 3 products); P fragments are LOCAL ----
#pragma unroll
        for (int kc = 0; kc < 4; kc++) {
            uint32_t ah[4], al[4];
#pragma unroll
            for (int i = 0; i < 4; i++) {
                float va = (i & 2) ? s[2 * kc + 1][(i & 1) * 2]
                                   : s[2 * kc][(i & 1) * 2];
                float vb = (i & 2) ? s[2 * kc + 1][(i & 1) * 2 + 1]
                                   : s[2 * kc][(i & 1) * 2 + 1];
                uint32_t h = pack2(va, vb);
                ah[i] = h;
                al[i] = pack2(va - lowf(h), vb - highf(h));
            }
#pragma unroll
            for (int nt = 0; nt < 8; nt++) {
                const uint32_t* rp = Vs + nt * 8 * VPITCH + vofs + kc * 8;
                uint2 vh = *(const uint2*)(rp);
                uint2 vl = *(const uint2*)(rp + 32);
                mmab(o[nt], ah, vh.x, vh.y);
                mmab(o[nt], al, vh.x, vh.y);
                mmab(o[nt], ah, vl.x, vl.y);
            }
        }
    }

    // ---- epilogue: normalize, store att + row norms ----
    float inv0 = 1.f / l0, inv1 = 1.f / l1;
    float* Ag = g_att[widx];
    int row0 = R + r, row1 = R + r + 8;
    float n0 = 0.f, n1 = 0.f;
#pragma unroll
    for (int nt = 0; nt < 8; nt++) {
        float2 v0 = make_float2(o[nt][0] * inv0, o[nt][1] * inv0);
        float2 v1 = make_float2(o[nt][2] * inv1, o[nt][3] * inv1);
        *(float2*)(Ag + row0 * D + nt * 8 + 2 * c) = v0;
        *(float2*)(Ag + row1 * D + nt * 8 + 2 * c) = v1;
        n0 += v0.x * v0.x + v0.y * v0.y;
        n1 += v1.x * v1.x + v1.y * v1.y;
    }
    n0 += __shfl_xor_sync(0xffffffffu, n0, 1);
    n0 += __shfl_xor_sync(0xffffffffu, n0, 2);
    n1 += __shfl_xor_sync(0xffffffffu, n1, 1);
    n1 += __shfl_xor_sync(0xffffffffu, n1, 2);
    if (c == 0) {
        g_nrm[widx][row0] = n0;
        g_nrm[widx][row1] = n1;
    }
}

// ---------------- 3) pairwise RBF (FFMA2, unchanged) -----------------------
__global__ __launch_bounds__(256, 2)
void pair_kernel(float* __restrict__ out)
{
    extern __shared__ float4 sm4[];
    float4* XA = sm4;
    float4* YA = sm4 + 2048;
    int tid = threadIdx.x;
    int tx = tid & 15, ty = tid >> 4;
    int i0 = blockIdx.x * 128, j0 = blockIdx.y * 128;
    const float* xa = g_att[0];
    const float* ya = g_att[1];

    for (int e = tid; e < 8192; e += 256) {
        int r = e >> 6, c = e & 63;
        ((float*)XA)[sw128i(c, r >> 2) * 4 + (r & 3)] = xa[(i0 + r) * D + c];
        ((float*)YA)[sw128i(c, r >> 2) * 4 + (r & 3)] = ya[(j0 + r) * D + c];
    }
    u64 acc2[8][4];
#pragma unroll
    for (int rr = 0; rr < 8; rr++)
#pragma unroll
        for (int p = 0; p < 4; p++) acc2[rr][p] = 0ull;
    __syncthreads();

#pragma unroll 8
    for (int k = 0; k < 64; k++) {
        float4 a0 = XA[sw128i(k, ty)];
        float4 a1 = XA[sw128i(k, 16 + ty)];
        ulonglong2 b0 = *(const ulonglong2*)(YA + sw128i(k, tx));
        ulonglong2 b1 = *(const ulonglong2*)(YA + sw128i(k, 16 + tx));
        u64 ar[8] = {dup2(a0.x), dup2(a0.y), dup2(a0.z), dup2(a0.w),
                     dup2(a1.x), dup2(a1.y), dup2(a1.z), dup2(a1.w)};
#pragma unroll
        for (int rr = 0; rr < 8; rr++) {
            ffma2(acc2[rr][0], ar[rr], b0.x);
            ffma2(acc2[rr][1], ar[rr], b0.y);
            ffma2(acc2[rr][2], ar[rr], b1.x);
            ffma2(acc2[rr][3], ar[rr], b1.y);
        }
    }
    float acc[8][8];
#pragma unroll
    for (int rr = 0; rr < 8; rr++)
#pragma unroll
        for (int p = 0; p < 4; p++) {
            float2 vv = unpk(acc2[rr][p]);
            acc[rr][2 * p] = vv.x; acc[rr][2 * p + 1] = vv.y;
        }
    int ri[8];
    float nx[8], ny[8];
#pragma unroll
    for (int q = 0; q < 8; q++) {
        ri[q] = i0 + ((q < 4) ? (ty * 4 + q) : (64 + ty * 4 + q - 4));
        int cjq = j0 + ((q < 4) ? (tx * 4 + q) : (64 + tx * 4 + q - 4));
        nx[q] = g_nrm[0][ri[q]];
        ny[q] = g_nrm[1][cjq];
    }
#pragma unroll
    for (int rr = 0; rr < 8; rr++) {
        float4 v0 = make_float4(__expf(2.f * acc[rr][0] - nx[rr] - ny[0]),
                                __expf(2.f * acc[rr][1] - nx[rr] - ny[1]),
                                __expf(2.f * acc[rr][2] - nx[rr] - ny[2]),
                                __expf(2.f * acc[rr][3] - nx[rr] - ny[3]));
        float4 v1 = make_float4(__expf(2.f * acc[rr][4] - nx[rr] - ny[4]),
                                __expf(2.f * acc[rr][5] - nx[rr] - ny[5]),
                                __expf(2.f * acc[rr][6] - nx[rr] - ny[6]),
                                __expf(2.f * acc[rr][7] - nx[rr] - ny[7]));
        float* rowp = out + (size_t)ri[rr] * NPTS;
        *(float4*)(rowp + j0 + tx * 4) = v0;
        *(float4*)(rowp + j0 + 64 + tx * 4) = v1;
    }
}

// ---------------- launcher -------------------------------------------------
extern "C" void kernel_launch(void* const* d_in, const int* in_sizes, int n_in,
                              void* d_out, int out_size)
{
    const float* Wq = (const float*)d_in[0];
    const float* Wk = (const float*)d_in[1];
    const float* x  = (const float*)d_in[2];
    const float* y  = (const float*)d_in[3];
    float* out = (float*)d_out;

    const int attn_smem = (64 * KPITCH + 64 * VPITCH) * 4;   // 36864 B
    cudaFuncSetAttribute(attn_mma, cudaFuncAttributeMaxDynamicSharedMemorySize, attn_smem);
    cudaFuncSetAttribute(pair_kernel, cudaFuncAttributeMaxDynamicSharedMemorySize, 64 * 1024);

    proj_kernel<<<dim3(NPTS / 64, 2), dim3(64, 4)>>>(x, y, Wq, Wk);
    pack_kernel<<<dim3((NPTS * 32 + NPTS * 32) / 256, 2), 256>>>();
    attn_mma<<<dim3(NPTS / 64, 2), 128, attn_smem>>>();
    pair_kernel<<<dim3(NPTS / 128, NPTS / 128), 256, 64 * 1024>>>(out);
}

// round 14
// speedup vs baseline: 2.1157x; 1.0744x over previous
#include <cuda_runtime.h>
#include <cstdint>

#define NPTS 8192
#define D 64
#define C1 0.18033688011111793f   // 0.125 * log2(e)
#define LOG2E 1.4426950408889634f
#define KPITCH 72                 // words/row: 2 regions of 32 + 8 pad (mod 32 == 8)
#define VPITCH 72
#define APITCH 72

typedef unsigned long long u64;

// ---------------- scratch globals ------------------------------------------
__device__ float g_q[2][NPTS * D];
__device__ float g_k[2][NPTS * D];
__device__ float g_vt[2][D * NPTS];                       // inputs transposed [d][n]
__device__ __align__(16) uint32_t g_kb[2][NPTS][KPITCH];  // K bf16 2-limb, frag-ready
__device__ __align__(16) uint32_t g_vb[2][NPTS / 64][D][VPITCH]; // V^T bf16 2-limb
__device__ float g_att[2][NPTS * D];
__device__ __align__(16) uint32_t g_ab[2][NPTS][APITCH];  // att bf16 2-limb, frag-ready
__device__ float g_nrm[2][NPTS];

// ---------------- bf16 mma helpers -----------------------------------------
__device__ __forceinline__ uint32_t pack2(float lo, float hi) {
    uint32_t d; asm("cvt.rn.bf16x2.f32 %0, %1, %2;" : "=r"(d) : "f"(hi), "f"(lo));
    return d;
}
__device__ __forceinline__ float lowf(uint32_t w)  { return __uint_as_float(w << 16); }
__device__ __forceinline__ float highf(uint32_t w) { return __uint_as_float(w & 0xffff0000u); }
__device__ __forceinline__ float ex2(float x) {
    float r; asm("ex2.approx.f32 %0, %1;" : "=f"(r) : "f"(x)); return r;
}
__device__ __forceinline__ void mmab(float* d, const uint32_t* a, uint32_t b0, uint32_t b1) {
    asm volatile(
        "mma.sync.aligned.m16n8k16.row.col.f32.bf16.bf16.f32 "
        "{%0,%1,%2,%3},{%4,%5,%6,%7},{%8,%9},{%0,%1,%2,%3};"
        : "+f"(d[0]), "+f"(d[1]), "+f"(d[2]), "+f"(d[3])
        : "r"(a[0]), "r"(a[1]), "r"(a[2]), "r"(a[3]), "r"(b0), "r"(b1));
}
// interleaved position for pair-index p: (b0,b1) of fragments land adjacent
__device__ __forceinline__ int ppos(int p) {
    int kc = p >> 3, q = p & 7;
    return kc * 8 + ((q < 4) ? 2 * q : 2 * q - 7);
}

// ---------------- 1) proj: Q/K fp32 + V^T fp32 -----------------------------
__global__ void proj_kernel(const float* __restrict__ x, const float* __restrict__ y,
                            const float* __restrict__ Wq, const float* __restrict__ Wk)
{
    __shared__ float wq[D * D], wk[D * D];
    __shared__ float xs[64][65];
    int tx = threadIdx.x, ty = threadIdx.y, tid = ty * 64 + tx;
    for (int i = tid; i < D * D; i += 256) { wq[i] = Wq[i]; wk[i] = Wk[i]; }
    int w = blockIdx.y;
    const float* in = w ? y : x;
    int row0 = blockIdx.x * 64;
    for (int e = tid; e < 64 * D; e += 256) xs[e >> 6][e & 63] = in[row0 * D + e];
    __syncthreads();

    for (int rl = ty; rl < 64; rl += 4) {
        float aq = 0.f, ak = 0.f;
#pragma unroll
        for (int k = 0; k < D; k++) {
            float v = xs[rl][k];
            aq = fmaf(v, wq[k * D + tx], aq);
            ak = fmaf(v, wk[k * D + tx], ak);
        }
        int idx = (row0 + rl) * D + tx;
        g_q[w][idx] = aq;
        g_k[w][idx] = ak;
    }
    for (int e = tid; e < 64 * D; e += 256) {
        int d = e >> 6, r = e & 63;
        g_vt[w][d * NPTS + row0 + r] = xs[r][d];
    }
}

// ---------------- 1b) pack K (2-limb) and V^T (2-limb) into bf16x2 ---------
__global__ void pack_kernel()
{
    int w = blockIdx.y;
    int idx = blockIdx.x * 256 + threadIdx.x;
    if (idx < NPTS * 32) {               // K: (j, pair p)
        int j = idx >> 5, p = idx & 31;
        float2 v = *(const float2*)(g_k[w] + j * D + 2 * p);
        uint32_t h = pack2(v.x, v.y);
        float r0 = v.x - lowf(h), r1 = v.y - highf(h);
        uint32_t m = pack2(r0, r1);
        int pos = ppos(p);
        g_kb[w][j][pos]      = h;
        g_kb[w][j][32 + pos] = m;
    } else {                             // V: (tile t, d, pair p)
        int i2 = idx - NPTS * 32;
        int t = i2 >> 11, d = (i2 >> 5) & 63, p = i2 & 31;
        float2 v = *(const float2*)(g_vt[w] + d * NPTS + t * 64 + 2 * p);
        uint32_t h = pack2(v.x, v.y);
        float r0 = v.x - lowf(h), r1 = v.y - highf(h);
        uint32_t l = pack2(r0, r1);
        int pos = ppos(p);
        g_vb[w][t][d][pos]      = h;
        g_vb[w][t][d][32 + pos] = l;
    }
}

// ---------------- 2) bf16 mma.sync flash attention -------------------------
// 4 warps, BM=64 (16 rows/warp), BN=64. QK: 2-limb 3-mma; PV: 2-limb 3-mma.
__global__ __launch_bounds__(128, 2)
void attn_mma()
{
    extern __shared__ uint32_t smw[];
    uint32_t* Ks = smw;                 // [64][KPITCH]
    uint32_t* Vs = smw + 64 * KPITCH;   // [64][VPITCH]

    int tid = threadIdx.x;
    int lane = tid & 31, w4 = tid >> 5;
    int r = lane >> 2, c = lane & 3;
    int widx = blockIdx.y;
    int R = blockIdx.x * 64 + 16 * w4;

    const float* Qg = g_q[widx];

    // persistent Q fragments: 2 limbs x 4 k-chunks x 4 regs
    uint32_t qh[4][4], qm[4][4];
#pragma unroll
    for (int kc = 0; kc < 4; kc++)
#pragma unroll
        for (int i = 0; i < 4; i++) {
            int row = R + r + 8 * (i & 1);
            int col = kc * 16 + 2 * c + 8 * (i >> 1);
            float2 q2 = *(const float2*)(Qg + row * D + col);
            uint32_t h = pack2(q2.x, q2.y);
            float r0 = q2.x - lowf(h), r1 = q2.y - highf(h);
            qh[kc][i] = h; qm[kc][i] = pack2(r0, r1);
        }

    float o[8][4];
#pragma unroll
    for (int nt = 0; nt < 8; nt++)
#pragma unroll
        for (int e = 0; e < 4; e++) o[nt][e] = 0.f;
    float m0 = -1e30f, m1 = -1e30f, l0 = 0.f, l1 = 0.f;

    int bofs = r * KPITCH + 2 * c;
    int vofs = r * VPITCH + 2 * c;

    for (int t = 0; t < NPTS / 64; t++) {
        __syncthreads();   // previous tile's reads done before restaging
        {
            const uint4* src = (const uint4*)(&g_kb[widx][t * 64][0]);
            uint4* dst = (uint4*)Ks;
            for (int i = tid; i < 64 * (KPITCH / 4); i += 128) dst[i] = src[i];
            const uint4* srcv = (const uint4*)(&g_vb[widx][t][0][0]);
            uint4* dstv = (uint4*)Vs;
            for (int i = tid; i < 64 * (VPITCH / 4); i += 128) dstv[i] = srcv[i];
        }
        __syncthreads();

        // ---- S = Q K^T (2-limb bf16, 3 products) ----
        float s[8][4];
#pragma unroll
        for (int nt = 0; nt < 8; nt++)
#pragma unroll
            for (int e = 0; e < 4; e++) s[nt][e] = 0.f;

#pragma unroll
        for (int kc = 0; kc < 4; kc++) {
#pragma unroll
            for (int nt = 0; nt < 8; nt++) {
                const uint32_t* rp = Ks + nt * 8 * KPITCH + bofs + kc * 8;
                uint2 bh = *(const uint2*)(rp);
                uint2 bm = *(const uint2*)(rp + 32);
                mmab(s[nt], qh[kc], bh.x, bh.y);
                mmab(s[nt], qm[kc], bh.x, bh.y);
                mmab(s[nt], qh[kc], bm.x, bm.y);
            }
        }

        // ---- online softmax (rows r, r+8; quad-replicated) ----
        float mr0 = -1e30f, mr1 = -1e30f;
#pragma unroll
        for (int nt = 0; nt < 8; nt++) {
            mr0 = fmaxf(mr0, fmaxf(s[nt][0], s[nt][1]));
            mr1 = fmaxf(mr1, fmaxf(s[nt][2], s[nt][3]));
        }
        mr0 = fmaxf(mr0, __shfl_xor_sync(0xffffffffu, mr0, 1));
        mr0 = fmaxf(mr0, __shfl_xor_sync(0xffffffffu, mr0, 2));
        mr1 = fmaxf(mr1, __shfl_xor_sync(0xffffffffu, mr1, 1));
        mr1 = fmaxf(mr1, __shfl_xor_sync(0xffffffffu, mr1, 2));
        float mn0 = fmaxf(m0, mr0), mn1 = fmaxf(m1, mr1);
        float corr0 = ex2((m0 - mn0) * C1), corr1 = ex2((m1 - mn1) * C1);
        m0 = mn0; m1 = mn1;

        float sum0 = 0.f, sum1 = 0.f;
#pragma unroll
        for (int nt = 0; nt < 8; nt++) {
            s[nt][0] = ex2((s[nt][0] - mn0) * C1);
            s[nt][1] = ex2((s[nt][1] - mn0) * C1);
            s[nt][2] = ex2((s[nt][2] - mn1) * C1);
            s[nt][3] = ex2((s[nt][3] - mn1) * C1);
            sum0 += s[nt][0] + s[nt][1];
            sum1 += s[nt][2] + s[nt][3];
        }
        sum0 += __shfl_xor_sync(0xffffffffu, sum0, 1);
        sum0 += __shfl_xor_sync(0xffffffffu, sum0, 2);
        sum1 += __shfl_xor_sync(0xffffffffu, sum1, 1);
        sum1 += __shfl_xor_sync(0xffffffffu, sum1, 2);
        l0 = l0 * corr0 + sum0;
        l1 = l1 * corr1 + sum1;
#pragma unroll
        for (int nt = 0; nt < 8; nt++) {
            o[nt][0] *= corr0; o[nt][1] *= corr0;
            o[nt][2] *= corr1; o[nt][3] *= corr1;
        }

        // ---- O += P V (2-limb bf16, 3 products); P fragments are LOCAL ----
#pragma unroll
        for (int kc = 0; kc < 4; kc++) {
            uint32_t ah[4], al[4];
#pragma unroll
            for (int i = 0; i < 4; i++) {
                float va = (i & 2) ? s[2 * kc + 1][(i & 1) * 2]
                                   : s[2 * kc][(i & 1) * 2];
                float vb = (i & 2) ? s[2 * kc + 1][(i & 1) * 2 + 1]
                                   : s[2 * kc][(i & 1) * 2 + 1];
                uint32_t h = pack2(va, vb);
                ah[i] = h;
                al[i] = pack2(va - lowf(h), vb - highf(h));
            }
#pragma unroll
            for (int nt = 0; nt < 8; nt++) {
                const uint32_t* rp = Vs + nt * 8 * VPITCH + vofs + kc * 8;
                uint2 vh = *(const uint2*)(rp);
                uint2 vl = *(const uint2*)(rp + 32);
                mmab(o[nt], ah, vh.x, vh.y);
                mmab(o[nt], al, vh.x, vh.y);
                mmab(o[nt], ah, vl.x, vl.y);
            }
        }
    }

    // ---- epilogue: normalize, store att + row norms ----
    float inv0 = 1.f / l0, inv1 = 1.f / l1;
    float* Ag = g_att[widx];
    int row0 = R + r, row1 = R + r + 8;
    float n0 = 0.f, n1 = 0.f;
#pragma unroll
    for (int nt = 0; nt < 8; nt++) {
        float2 v0 = make_float2(o[nt][0] * inv0, o[nt][1] * inv0);
        float2 v1 = make_float2(o[nt][2] * inv1, o[nt][3] * inv1);
        *(float2*)(Ag + row0 * D + nt * 8 + 2 * c) = v0;
        *(float2*)(Ag + row1 * D + nt * 8 + 2 * c) = v1;
        n0 += v0.x * v0.x + v0.y * v0.y;
        n1 += v1.x * v1.x + v1.y * v1.y;
    }
    n0 += __shfl_xor_sync(0xffffffffu, n0, 1);
    n0 += __shfl_xor_sync(0xffffffffu, n0, 2);
    n1 += __shfl_xor_sync(0xffffffffu, n1, 1);
    n1 += __shfl_xor_sync(0xffffffffu, n1, 2);
    if (c == 0) {
        g_nrm[widx][row0] = n0;
        g_nrm[widx][row1] = n1;
    }
}

// ---------------- 2b) pack att into 2-limb bf16 frag-ready rows ------------
__global__ void pack_att_kernel()
{
    int w = blockIdx.y;
    int idx = blockIdx.x * 256 + threadIdx.x;   // NPTS*32
    int row = idx >> 5, p = idx & 31;
    float2 v = *(const float2*)(g_att[w] + row * D + 2 * p);
    uint32_t h = pack2(v.x, v.y);
    uint32_t l = pack2(v.x - lowf(h), v.y - highf(h));
    int pos = ppos(p);
    g_ab[w][row][pos]      = h;
    g_ab[w][row][32 + pos] = l;
}

// ---------------- 3) pairwise RBF via bf16 mma -----------------------------
// 128x128 tile per CTA, 8 warps as 4(m) x 2(n); warp tile 32x64.
__global__ __launch_bounds__(256, 2)
void pair_mma(float* __restrict__ out)
{
    extern __shared__ uint32_t smw[];
    uint32_t* Xs = smw;                   // [128][APITCH]
    uint32_t* Ys = smw + 128 * APITCH;

    int tid = threadIdx.x;
    int lane = tid & 31, warp = tid >> 5;
    int wm = warp >> 1, wn = warp & 1;
    int r = lane >> 2, c = lane & 3;
    int i0 = blockIdx.x * 128, j0 = blockIdx.y * 128;

    // stage both tiles (flat copy; global layout == smem layout)
    {
        const uint4* sx = (const uint4*)(&g_ab[0][i0][0]);
        const uint4* sy = (const uint4*)(&g_ab[1][j0][0]);
        uint4* dx = (uint4*)Xs;
        uint4* dy = (uint4*)Ys;
        for (int i = tid; i < 128 * (APITCH / 4); i += 256) {
            dx[i] = sx[i];
            dy[i] = sy[i];
        }
    }
    __syncthreads();

    float acc[2][8][4];
#pragma unroll
    for (int mt = 0; mt < 2; mt++)
#pragma unroll
        for (int nt = 0; nt < 8; nt++)
#pragma unroll
            for (int e = 0; e < 4; e++) acc[mt][nt][e] = 0.f;

#pragma unroll
    for (int kc = 0; kc < 4; kc++) {
        uint32_t ah[2][4], al[2][4];
#pragma unroll
        for (int mt = 0; mt < 2; mt++) {
            const uint32_t* pa0 = Xs + (wm * 32 + mt * 16 + r) * APITCH + 2 * c + kc * 8;
            const uint32_t* pa1 = pa0 + 8 * APITCH;
            uint2 h0 = *(const uint2*)(pa0), h1 = *(const uint2*)(pa1);
            uint2 l0 = *(const uint2*)(pa0 + 32), l1 = *(const uint2*)(pa1 + 32);
            ah[mt][0] = h0.x; ah[mt][1] = h1.x; ah[mt][2] = h0.y; ah[mt][3] = h1.y;
            al[mt][0] = l0.x; al[mt][1] = l1.x; al[mt][2] = l0.y; al[mt][3] = l1.y;
        }
#pragma unroll
        for (int nt = 0; nt < 8; nt++) {
            const uint32_t* pb = Ys + (wn * 64 + nt * 8 + r) * APITCH + 2 * c + kc * 8;
            uint2 bh = *(const uint2*)(pb);
            uint2 bl = *(const uint2*)(pb + 32);
#pragma unroll
            for (int mt = 0; mt < 2; mt++) {
                mmab(acc[mt][nt], ah[mt], bh.x, bh.y);
                mmab(acc[mt][nt], al[mt], bh.x, bh.y);
                mmab(acc[mt][nt], ah[mt], bl.x, bl.y);
            }
        }
    }

    // ---- epilogue: exp(2*dot - nx - ny), float2 stores ----
    float ny[8][2];
#pragma unroll
    for (int nt = 0; nt < 8; nt++) {
        int j = j0 + wn * 64 + nt * 8 + 2 * c;
        ny[nt][0] = g_nrm[1][j];
        ny[nt][1] = g_nrm[1][j + 1];
    }
#pragma unroll
    for (int mt = 0; mt < 2; mt++) {
        int rowA = i0 + wm * 32 + mt * 16 + r;
        float nx0 = g_nrm[0][rowA];
        float nx1 = g_nrm[0][rowA + 8];
        float* rp0 = out + (size_t)rowA * NPTS + j0 + wn * 64;
        float* rp1 = rp0 + (size_t)8 * NPTS;
#pragma unroll
        for (int nt = 0; nt < 8; nt++) {
            float2 v0, v1;
            v0.x = ex2((2.f * acc[mt][nt][0] - nx0 - ny[nt][0]) * LOG2E);
            v0.y = ex2((2.f * acc[mt][nt][1] - nx0 - ny[nt][1]) * LOG2E);
            v1.x = ex2((2.f * acc[mt][nt][2] - nx1 - ny[nt][0]) * LOG2E);
            v1.y = ex2((2.f * acc[mt][nt][3] - nx1 - ny[nt][1]) * LOG2E);
            *(float2*)(rp0 + nt * 8 + 2 * c) = v0;
            *(float2*)(rp1 + nt * 8 + 2 * c) = v1;
        }
    }
}

// ---------------- launcher -------------------------------------------------
extern "C" void kernel_launch(void* const* d_in, const int* in_sizes, int n_in,
                              void* d_out, int out_size)
{
    const float* Wq = (const float*)d_in[0];
    const float* Wk = (const float*)d_in[1];
    const float* x  = (const float*)d_in[2];
    const float* y  = (const float*)d_in[3];
    float* out = (float*)d_out;

    const int attn_smem = (64 * KPITCH + 64 * VPITCH) * 4;     // 36864 B
    const int pair_smem = 2 * 128 * APITCH * 4;                // 73728 B
    cudaFuncSetAttribute(attn_mma, cudaFuncAttributeMaxDynamicSharedMemorySize, attn_smem);
    cudaFuncSetAttribute(pair_mma, cudaFuncAttributeMaxDynamicSharedMemorySize, pair_smem);

    proj_kernel<<<dim3(NPTS / 64, 2), dim3(64, 4)>>>(x, y, Wq, Wk);
    pack_kernel<<<dim3((NPTS * 32 + NPTS * 32) / 256, 2), 256>>>();
    attn_mma<<<dim3(NPTS / 64, 2), 128, attn_smem>>>();
    pack_att_kernel<<<dim3(NPTS * 32 / 256, 2), 256>>>();
    pair_mma<<<dim3(NPTS / 128, NPTS / 128), 256, pair_smem>>>(out);
}

// round 17
// speedup vs baseline: 3.1468x; 1.4874x over previous
#include <cuda_runtime.h>
#include <cstdint>

#define NPTS 8192
#define D 64
#define C1 0.18033688011111793f   // 0.125 * log2(e)
#define LOG2E 1.4426950408889634f
#define KPITCH 72                 // words/row: 2 regions of 32 + 8 pad (mod 32 == 8)
#define VPITCH 72
#define APITCH 72
#define TILE_W (64 * KPITCH + 64 * VPITCH)   // words per K+V tile buffer

typedef unsigned long long u64;

// ---------------- scratch globals ------------------------------------------
__device__ float g_q[2][NPTS * D];
__device__ float g_k[2][NPTS * D];
__device__ float g_vt[2][D * NPTS];                       // inputs transposed [d][n]
__device__ __align__(16) uint32_t g_kb[2][NPTS][KPITCH];  // K bf16 2-limb, frag-ready
__device__ __align__(16) uint32_t g_vb[2][NPTS / 64][D][VPITCH]; // V^T bf16 2-limb
__device__ float g_att[2][NPTS * D];
__device__ __align__(16) uint32_t g_ab[2][NPTS][APITCH];  // att bf16 2-limb, frag-ready
__device__ float g_nrm[2][NPTS];

// ---------------- bf16 mma helpers -----------------------------------------
__device__ __forceinline__ uint32_t pack2(float lo, float hi) {
    uint32_t d; asm("cvt.rn.bf16x2.f32 %0, %1, %2;" : "=r"(d) : "f"(hi), "f"(lo));
    return d;
}
__device__ __forceinline__ float lowf(uint32_t w)  { return __uint_as_float(w << 16); }
__device__ __forceinline__ float highf(uint32_t w) { return __uint_as_float(w & 0xffff0000u); }
__device__ __forceinline__ float ex2(float x) {
    float r; asm("ex2.approx.f32 %0, %1;" : "=f"(r) : "f"(x)); return r;
}
__device__ __forceinline__ void mmab(float* d, const uint32_t* a, uint32_t b0, uint32_t b1) {
    asm volatile(
        "mma.sync.aligned.m16n8k16.row.col.f32.bf16.bf16.f32 "
        "{%0,%1,%2,%3},{%4,%5,%6,%7},{%8,%9},{%0,%1,%2,%3};"
        : "+f"(d[0]), "+f"(d[1]), "+f"(d[2]), "+f"(d[3])
        : "r"(a[0]), "r"(a[1]), "r"(a[2]), "r"(a[3]), "r"(b0), "r"(b1));
}
// interleaved position for pair-index p: (b0,b1) of fragments land adjacent
__device__ __forceinline__ int ppos(int p) {
    int kc = p >> 3, q = p & 7;
    return kc * 8 + ((q < 4) ? 2 * q : 2 * q - 7);
}
__device__ __forceinline__ void cpasync16(uint32_t daddr, const void* src) {
    asm volatile("cp.async.cg.shared.global [%0], [%1], 16;"
                 :: "r"(daddr), "l"(src) : "memory");
}

// ---------------- 1) proj: Q/K fp32 + V^T fp32 -----------------------------
__global__ void proj_kernel(const float* __restrict__ x, const float* __restrict__ y,
                            const float* __restrict__ Wq, const float* __restrict__ Wk)
{
    __shared__ float wq[D * D], wk[D * D];
    __shared__ float xs[64][65];
    int tx = threadIdx.x, ty = threadIdx.y, tid = ty * 64 + tx;
    for (int i = tid; i < D * D; i += 256) { wq[i] = Wq[i]; wk[i] = Wk[i]; }
    int w = blockIdx.y;
    const float* in = w ? y : x;
    int row0 = blockIdx.x * 64;
    for (int e = tid; e < 64 * D; e += 256) xs[e >> 6][e & 63] = in[row0 * D + e];
    __syncthreads();

    for (int rl = ty; rl < 64; rl += 4) {
        float aq = 0.f, ak = 0.f;
#pragma unroll
        for (int k = 0; k < D; k++) {
            float v = xs[rl][k];
            aq = fmaf(v, wq[k * D + tx], aq);
            ak = fmaf(v, wk[k * D + tx], ak);
        }
        int idx = (row0 + rl) * D + tx;
        g_q[w][idx] = aq;
        g_k[w][idx] = ak;
    }
    for (int e = tid; e < 64 * D; e += 256) {
        int d = e >> 6, r = e & 63;
        g_vt[w][d * NPTS + row0 + r] = xs[r][d];
    }
}

// ---------------- 1b) pack K (2-limb) and V^T (2-limb) into bf16x2 ---------
__global__ void pack_kernel()
{
    int w = blockIdx.y;
    int idx = blockIdx.x * 256 + threadIdx.x;
    if (idx < NPTS * 32) {               // K: (j, pair p)
        int j = idx >> 5, p = idx & 31;
        float2 v = *(const float2*)(g_k[w] + j * D + 2 * p);
        uint32_t h = pack2(v.x, v.y);
        float r0 = v.x - lowf(h), r1 = v.y - highf(h);
        uint32_t m = pack2(r0, r1);
        int pos = ppos(p);
        g_kb[w][j][pos]      = h;
        g_kb[w][j][32 + pos] = m;
    } else {                             // V: (tile t, d, pair p)
        int i2 = idx - NPTS * 32;
        int t = i2 >> 11, d = (i2 >> 5) & 63, p = i2 & 31;
        float2 v = *(const float2*)(g_vt[w] + d * NPTS + t * 64 + 2 * p);
        uint32_t h = pack2(v.x, v.y);
        float r0 = v.x - lowf(h), r1 = v.y - highf(h);
        uint32_t l = pack2(r0, r1);
        int pos = ppos(p);
        g_vb[w][t][d][pos]      = h;
        g_vb[w][t][d][32 + pos] = l;
    }
}

// ---------------- 2) bf16 mma.sync flash attention -------------------------
// BM=128 per CTA, 8 warps (16 rows each), BN=64, cp.async double buffering.
// QK: 2-limb 3-mma; PV: 2-limb 3-mma.
__global__ __launch_bounds__(256, 1)
void attn_mma()
{
    extern __shared__ uint32_t smw[];
    uint32_t sbase = (uint32_t)__cvta_generic_to_shared(smw);

    int tid = threadIdx.x;
    int lane = tid & 31, warp = tid >> 5;
    int r = lane >> 2, c = lane & 3;
    int widx = blockIdx.y;
    int R = blockIdx.x * 128 + 16 * warp;

    const float* Qg = g_q[widx];

    // persistent Q fragments: 2 limbs x 4 k-chunks x 4 regs
    uint32_t qh[4][4], qm[4][4];
#pragma unroll
    for (int kc = 0; kc < 4; kc++)
#pragma unroll
        for (int i = 0; i < 4; i++) {
            int row = R + r + 8 * (i & 1);
            int col = kc * 16 + 2 * c + 8 * (i >> 1);
            float2 q2 = *(const float2*)(Qg + row * D + col);
            uint32_t h = pack2(q2.x, q2.y);
            float r0 = q2.x - lowf(h), r1 = q2.y - highf(h);
            qh[kc][i] = h; qm[kc][i] = pack2(r0, r1);
        }

    float o[8][4];
#pragma unroll
    for (int nt = 0; nt < 8; nt++)
#pragma unroll
        for (int e = 0; e < 4; e++) o[nt][e] = 0.f;
    float m0 = -1e30f, m1 = -1e30f, l0 = 0.f, l1 = 0.f;

    int bofs = r * KPITCH + 2 * c;
    int vofs = r * VPITCH + 2 * c;

    // stage tile t into buffer b: 2304 uint4 (exactly 9 per thread)
    auto stage = [&](int t, int b) {
        uint32_t dst = sbase + (uint32_t)b * TILE_W * 4;
        const uint4* sk = (const uint4*)(&g_kb[widx][t * 64][0]);
        const uint4* sv = (const uint4*)(&g_vb[widx][t][0][0]);
#pragma unroll
        for (int q = 0; q < 9; q++) {
            int i = tid + q * 256;
            if (i < 1152) cpasync16(dst + i * 16, sk + i);
            else          cpasync16(dst + (64 * KPITCH) * 4 + (i - 1152) * 16,
                                    sv + (i - 1152));
        }
        asm volatile("cp.async.commit_group;" ::: "memory");
    };

    stage(0, 0);

    for (int t = 0; t < NPTS / 64; t++) {
        int b = t & 1;
        if (t + 1 < NPTS / 64) {
            stage(t + 1, b ^ 1);
            asm volatile("cp.async.wait_group 1;" ::: "memory");
        } else {
            asm volatile("cp.async.wait_group 0;" ::: "memory");
        }
        __syncthreads();   // staged buffer b visible to all warps

        const uint32_t* Ks = smw + b * TILE_W;
        const uint32_t* Vs = Ks + 64 * KPITCH;

        // ---- S = Q K^T (2-limb bf16, 3 products) ----
        float s[8][4];
#pragma unroll
        for (int nt = 0; nt < 8; nt++)
#pragma unroll
            for (int e = 0; e < 4; e++) s[nt][e] = 0.f;

#pragma unroll
        for (int kc = 0; kc < 4; kc++) {
#pragma unroll
            for (int nt = 0; nt < 8; nt++) {
                const uint32_t* rp = Ks + nt * 8 * KPITCH + bofs + kc * 8;
                uint2 bh = *(const uint2*)(rp);
                uint2 bm = *(const uint2*)(rp + 32);
                mmab(s[nt], qh[kc], bh.x, bh.y);
                mmab(s[nt], qm[kc], bh.x, bh.y);
                mmab(s[nt], qh[kc], bm.x, bm.y);
            }
        }

        // ---- online softmax (rows r, r+8; quad-replicated) ----
        float mr0 = -1e30f, mr1 = -1e30f;
#pragma unroll
        for (int nt = 0; nt < 8; nt++) {
            mr0 = fmaxf(mr0, fmaxf(s[nt][0], s[nt][1]));
            mr1 = fmaxf(mr1, fmaxf(s[nt][2], s[nt][3]));
        }
        mr0 = fmaxf(mr0, __shfl_xor_sync(0xffffffffu, mr0, 1));
        mr0 = fmaxf(mr0, __shfl_xor_sync(0xffffffffu, mr0, 2));
        mr1 = fmaxf(mr1, __shfl_xor_sync(0xffffffffu, mr1, 1));
        mr1 = fmaxf(mr1, __shfl_xor_sync(0xffffffffu, mr1, 2));
        float mn0 = fmaxf(m0, mr0), mn1 = fmaxf(m1, mr1);
        float corr0 = ex2((m0 - mn0) * C1), corr1 = ex2((m1 - mn1) * C1);
        m0 = mn0; m1 = mn1;

        float sum0 = 0.f, sum1 = 0.f;
#pragma unroll
        for (int nt = 0; nt < 8; nt++) {
            s[nt][0] = ex2((s[nt][0] - mn0) * C1);
            s[nt][1] = ex2((s[nt][1] - mn0) * C1);
            s[nt][2] = ex2((s[nt][2] - mn1) * C1);
            s[nt][3] = ex2((s[nt][3] - mn1) * C1);
            sum0 += s[nt][0] + s[nt][1];
            sum1 += s[nt][2] + s[nt][3];
        }
        sum0 += __shfl_xor_sync(0xffffffffu, sum0, 1);
        sum0 += __shfl_xor_sync(0xffffffffu, sum0, 2);
        sum1 += __shfl_xor_sync(0xffffffffu, sum1, 1);
        sum1 += __shfl_xor_sync(0xffffffffu, sum1, 2);
        l0 = l0 * corr0 + sum0;
        l1 = l1 * corr1 + sum1;
#pragma unroll
        for (int nt = 0; nt < 8; nt++) {
            o[nt][0] *= corr0; o[nt][1] *= corr0;
            o[nt][2] *= corr1; o[nt][3] *= corr1;
        }

        // ---- O += P V (2-limb bf16, 3 products); P fragments are LOCAL ----
#pragma unroll
        for (int kc = 0; kc < 4; kc++) {
            uint32_t ah[4], al[4];
#pragma unroll
            for (int i = 0; i < 4; i++) {
                float va = (i & 2) ? s[2 * kc + 1][(i & 1) * 2]
                                   : s[2 * kc][(i & 1) * 2];
                float vb = (i & 2) ? s[2 * kc + 1][(i & 1) * 2 + 1]
                                   : s[2 * kc][(i & 1) * 2 + 1];
                uint32_t h = pack2(va, vb);
                ah[i] = h;
                al[i] = pack2(va - lowf(h), vb - highf(h));
            }
#pragma unroll
            for (int nt = 0; nt < 8; nt++) {
                const uint32_t* rp = Vs + nt * 8 * VPITCH + vofs + kc * 8;
                uint2 vh = *(const uint2*)(rp);
                uint2 vl = *(const uint2*)(rp + 32);
                mmab(o[nt], ah, vh.x, vh.y);
                mmab(o[nt], al, vh.x, vh.y);
                mmab(o[nt], ah, vl.x, vl.y);
            }
        }
        __syncthreads();   // all reads of buffer b done before t+2 overwrites it
    }

    // ---- epilogue: normalize, store att + row norms ----
    float inv0 = 1.f / l0, inv1 = 1.f / l1;
    float* Ag = g_att[widx];
    int row0 = R + r, row1 = R + r + 8;
    float n0 = 0.f, n1 = 0.f;
#pragma unroll
    for (int nt = 0; nt < 8; nt++) {
        float2 v0 = make_float2(o[nt][0] * inv0, o[nt][1] * inv0);
        float2 v1 = make_float2(o[nt][2] * inv1, o[nt][3] * inv1);
        *(float2*)(Ag + row0 * D + nt * 8 + 2 * c) = v0;
        *(float2*)(Ag + row1 * D + nt * 8 + 2 * c) = v1;
        n0 += v0.x * v0.x + v0.y * v0.y;
        n1 += v1.x * v1.x + v1.y * v1.y;
    }
    n0 += __shfl_xor_sync(0xffffffffu, n0, 1);
    n0 += __shfl_xor_sync(0xffffffffu, n0, 2);
    n1 += __shfl_xor_sync(0xffffffffu, n1, 1);
    n1 += __shfl_xor_sync(0xffffffffu, n1, 2);
    if (c == 0) {
        g_nrm[widx][row0] = n0;
        g_nrm[widx][row1] = n1;
    }
}

// ---------------- 2b) pack att into 2-limb bf16 frag-ready rows ------------
__global__ void pack_att_kernel()
{
    int w = blockIdx.y;
    int idx = blockIdx.x * 256 + threadIdx.x;   // NPTS*32
    int row = idx >> 5, p = idx & 31;
    float2 v = *(const float2*)(g_att[w] + row * D + 2 * p);
    uint32_t h = pack2(v.x, v.y);
    uint32_t l = pack2(v.x - lowf(h), v.y - highf(h));
    int pos = ppos(p);
    g_ab[w][row][pos]      = h;
    g_ab[w][row][32 + pos] = l;
}

// ---------------- 3) pairwise RBF via bf16 mma -----------------------------
// 128x128 tile per CTA, 8 warps as 4(m) x 2(n); warp tile 32x64.
__global__ __launch_bounds__(256, 2)
void pair_mma(float* __restrict__ out)
{
    extern __shared__ uint32_t smw[];
    uint32_t* Xs = smw;                   // [128][APITCH]
    uint32_t* Ys = smw + 128 * APITCH;

    int tid = threadIdx.x;
    int lane = tid & 31, warp = tid >> 5;
    int wm = warp >> 1, wn = warp & 1;
    int r = lane >> 2, c = lane & 3;
    int i0 = blockIdx.x * 128, j0 = blockIdx.y * 128;

    // stage both tiles (flat copy; global layout == smem layout)
    {
        const uint4* sx = (const uint4*)(&g_ab[0][i0][0]);
        const uint4* sy = (const uint4*)(&g_ab[1][j0][0]);
        uint4* dx = (uint4*)Xs;
        uint4* dy = (uint4*)Ys;
        for (int i = tid; i < 128 * (APITCH / 4); i += 256) {
            dx[i] = sx[i];
            dy[i] = sy[i];
        }
    }
    __syncthreads();

    float acc[2][8][4];
#pragma unroll
    for (int mt = 0; mt < 2; mt++)
#pragma unroll
        for (int nt = 0; nt < 8; nt++)
#pragma unroll
            for (int e = 0; e < 4; e++) acc[mt][nt][e] = 0.f;

#pragma unroll
    for (int kc = 0; kc < 4; kc++) {
        uint32_t ah[2][4], al[2][4];
#pragma unroll
        for (int mt = 0; mt < 2; mt++) {
            const uint32_t* pa0 = Xs + (wm * 32 + mt * 16 + r) * APITCH + 2 * c + kc * 8;
            const uint32_t* pa1 = pa0 + 8 * APITCH;
            uint2 h0 = *(const uint2*)(pa0), h1 = *(const uint2*)(pa1);
            uint2 l0 = *(const uint2*)(pa0 + 32), l1 = *(const uint2*)(pa1 + 32);
            ah[mt][0] = h0.x; ah[mt][1] = h1.x; ah[mt][2] = h0.y; ah[mt][3] = h1.y;
            al[mt][0] = l0.x; al[mt][1] = l1.x; al[mt][2] = l0.y; al[mt][3] = l1.y;
        }
#pragma unroll
        for (int nt = 0; nt < 8; nt++) {
            const uint32_t* pb = Ys + (wn * 64 + nt * 8 + r) * APITCH + 2 * c + kc * 8;
            uint2 bh = *(const uint2*)(pb);
            uint2 bl = *(const uint2*)(pb + 32);
#pragma unroll
            for (int mt = 0; mt < 2; mt++) {
                mmab(acc[mt][nt], ah[mt], bh.x, bh.y);
                mmab(acc[mt][nt], al[mt], bh.x, bh.y);
                mmab(acc[mt][nt], ah[mt], bl.x, bl.y);
            }
        }
    }

    // ---- epilogue: exp(2*dot - nx - ny), float2 stores ----
    float ny[8][2];
#pragma unroll
    for (int nt = 0; nt < 8; nt++) {
        int j = j0 + wn * 64 + nt * 8 + 2 * c;
        ny[nt][0] = g_nrm[1][j];
        ny[nt][1] = g_nrm[1][j + 1];
    }
#pragma unroll
    for (int mt = 0; mt < 2; mt++) {
        int rowA = i0 + wm * 32 + mt * 16 + r;
        float nx0 = g_nrm[0][rowA];
        float nx1 = g_nrm[0][rowA + 8];
        float* rp0 = out + (size_t)rowA * NPTS + j0 + wn * 64;
        float* rp1 = rp0 + (size_t)8 * NPTS;
#pragma unroll
        for (int nt = 0; nt < 8; nt++) {
            float2 v0, v1;
            v0.x = ex2((2.f * acc[mt][nt][0] - nx0 - ny[nt][0]) * LOG2E);
            v0.y = ex2((2.f * acc[mt][nt][1] - nx0 - ny[nt][1]) * LOG2E);
            v1.x = ex2((2.f * acc[mt][nt][2] - nx1 - ny[nt][0]) * LOG2E);
            v1.y = ex2((2.f * acc[mt][nt][3] - nx1 - ny[nt][1]) * LOG2E);
            *(float2*)(rp0 + nt * 8 + 2 * c) = v0;
            *(float2*)(rp1 + nt * 8 + 2 * c) = v1;
        }
    }
}

// ---------------- launcher -------------------------------------------------
extern "C" void kernel_launch(void* const* d_in, const int* in_sizes, int n_in,
                              void* d_out, int out_size)
{
    const float* Wq = (const float*)d_in[0];
    const float* Wk = (const float*)d_in[1];
    const float* x  = (const float*)d_in[2];
    const float* y  = (const float*)d_in[3];
    float* out = (float*)d_out;

    const int attn_smem = 2 * TILE_W * 4;                      // 73728 B
    const int pair_smem = 2 * 128 * APITCH * 4;                // 73728 B
    cudaFuncSetAttribute(attn_mma, cudaFuncAttributeMaxDynamicSharedMemorySize, attn_smem);
    cudaFuncSetAttribute(pair_mma, cudaFuncAttributeMaxDynamicSharedMemorySize, pair_smem);

    proj_kernel<<<dim3(NPTS / 64, 2), dim3(64, 4)>>>(x, y, Wq, Wk);
    pack_kernel<<<dim3((NPTS * 32 + NPTS * 32) / 256, 2), 256>>>();
    attn_mma<<<dim3(NPTS / 128, 2), 256, attn_smem>>>();
    pack_att_kernel<<<dim3(NPTS * 32 / 256, 2), 256>>>();
    pair_mma<<<dim3(NPTS / 128, NPTS / 128), 256, pair_smem>>>(out);
}